// round 5
// baseline (speedup 1.0000x reference)
#include <cuda_runtime.h>
#include <cuda_fp16.h>
#include <stdint.h>

#define DEVI __device__ __forceinline__

namespace {
constexpr int kB = 2, kS = 2048, kDM = 1024, kH = 16, kD = 64;
constexpr int kBS = kB * kS, kBH = kB * kH;
constexpr int ATTN_SMEM = 132096;
}

// Static scratch. Q/K/V pre-split fp16 hi/lo by projection kernels.
__device__ __half gQh[(size_t)kBH*kS*kD], gQl[(size_t)kBH*kS*kD]; // [bh][s][d] (x0.125)
__device__ __half gKh[(size_t)kBH*kS*kD], gKl[(size_t)kBH*kS*kD]; // [bh][s][d]
__device__ __half gVh[(size_t)kBH*kD*kS], gVl[(size_t)kBH*kD*kS]; // [bh][d][s]
__device__ float  g_C [(size_t)kBS*kDM];
__device__ float  g_rinv[(size_t)kBH*kS];

// ---------------- helpers ----------------
DEVI void mma16816(float c[4], const uint32_t a[4], const uint32_t b[2]) {
    asm volatile(
        "mma.sync.aligned.m16n8k16.row.col.f32.f16.f16.f32 "
        "{%0,%1,%2,%3}, {%4,%5,%6,%7}, {%8,%9}, {%0,%1,%2,%3};\n"
        : "+f"(c[0]), "+f"(c[1]), "+f"(c[2]), "+f"(c[3])
        : "r"(a[0]), "r"(a[1]), "r"(a[2]), "r"(a[3]), "r"(b[0]), "r"(b[1]));
}
DEVI void splitf(float x, __half& hi, __half& lo) {
    hi = __float2half_rn(x);
    lo = __float2half_rn(x - __half2float(hi));
}
DEVI void load_a(const __half* base, int st, uint32_t a[4]) {
    a[0] = *reinterpret_cast<const uint32_t*>(base);
    a[1] = *reinterpret_cast<const uint32_t*>(base + 8 * st);
    a[2] = *reinterpret_cast<const uint32_t*>(base + 8);
    a[3] = *reinterpret_cast<const uint32_t*>(base + 8 * st + 8);
}
DEVI void load_b(const __half* base, uint32_t b[2]) {
    b[0] = *reinterpret_cast<const uint32_t*>(base);
    b[1] = *reinterpret_cast<const uint32_t*>(base + 8);
}
DEVI float fexp(float x) {   // FFMA-only exp, |rel err| ~1e-7 for |x|<~10
    float t = x * 1.44269504f;
    float fn = rintf(t);
    float f = t - fn;
    float p = 1.33336498e-3f;
    p = fmaf(p, f, 9.61793093e-3f);
    p = fmaf(p, f, 5.55043924e-2f);
    p = fmaf(p, f, 2.40226507e-1f);
    p = fmaf(p, f, 6.93147182e-1f);
    p = fmaf(p, f, 1.0f);
    return __int_as_float(__float_as_int(p) + (((int)fn) << 23));
}
DEVI void cpasync16(uint32_t dst, const void* src) {
    asm volatile("cp.async.cg.shared.global [%0], [%1], 16;\n" :: "r"(dst), "l"(src));
}
DEVI void cpcommit() { asm volatile("cp.async.commit_group;\n" ::: "memory"); }
DEVI void cpwait0()  { asm volatile("cp.async.wait_group 0;\n" ::: "memory"); }
DEVI uint32_t s2u(const void* p) {
    uint32_t a;
    asm("{ .reg .u64 t; cvta.to.shared.u64 t, %1; cvt.u32.u64 %0, t; }" : "=r"(a) : "l"(p));
    return a;
}

// ---------------------------------------------------------------------------
// Shared projection mainloop: 128x128 tile, K=1024, 3-term split.
// wmode 0: W=[H][Dm][64] per-head (hc = head base);  wmode 1: W=[Dm][1024] (hc = col0)
// ---------------------------------------------------------------------------
DEVI void proj_mainloop(const float* Xb, const float* __restrict__ W, int wmode, int hc,
                        __half* Ah, __half* Al, __half* Bh, __half* Bl,
                        float acc[2][8][4], int tid, int wm, int wn, int qid, int tq)
{
    for (int kc = 0; kc < 32; kc++) {
        const int k0 = kc * 32;
#pragma unroll
        for (int p = 0; p < 4; p++) {                       // A: 128x32 fp32 -> split
            int r  = (tid >> 3) + p * 32;
            int c4 = (tid & 7) * 4;
            float4 v = *reinterpret_cast<const float4*>(Xb + (size_t)r * kDM + k0 + c4);
            __half h0,h1,h2,h3,l0,l1,l2,l3;
            splitf(v.x,h0,l0); splitf(v.y,h1,l1); splitf(v.z,h2,l2); splitf(v.w,h3,l3);
            *reinterpret_cast<__half2*>(Ah + r*40 + c4)     = __halves2half2(h0,h1);
            *reinterpret_cast<__half2*>(Ah + r*40 + c4 + 2) = __halves2half2(h2,h3);
            *reinterpret_cast<__half2*>(Al + r*40 + c4)     = __halves2half2(l0,l1);
            *reinterpret_cast<__half2*>(Al + r*40 + c4 + 2) = __halves2half2(l2,l3);
        }
#pragma unroll
        for (int p = 0; p < 16; p++) {                      // B^T: [n][k] 128x32
            int idx = p * 256 + tid;
            int n = idx & 127, kk = idx >> 7;
            float v = (wmode == 0)
                ? W[((size_t)(hc + (n >> 6)) * kDM + k0 + kk) * kD + (n & 63)]
                : W[(size_t)(k0 + kk) * kDM + hc + n];
            __half hi, lo; splitf(v, hi, lo);
            Bh[n*40 + kk] = hi; Bl[n*40 + kk] = lo;
        }
        __syncthreads();
#pragma unroll
        for (int ks = 0; ks < 2; ks++) {
            const int kf = ks * 16;
            uint32_t ah[2][4], al[2][4];
#pragma unroll
            for (int mi = 0; mi < 2; mi++) {
                int r = wm*32 + mi*16 + qid;
                load_a(Ah + r*40 + kf + tq*2, 40, ah[mi]);
                load_a(Al + r*40 + kf + tq*2, 40, al[mi]);
            }
#pragma unroll
            for (int ni = 0; ni < 8; ni++) {
                int n = wn*64 + ni*8 + qid;
                uint32_t bh[2], bl[2];
                load_b(Bh + n*40 + kf + tq*2, bh);
                load_b(Bl + n*40 + kf + tq*2, bl);
#pragma unroll
                for (int mi = 0; mi < 2; mi++) {
                    mma16816(acc[mi][ni], ah[mi], bh);
                    mma16816(acc[mi][ni], ah[mi], bl);
                    mma16816(acc[mi][ni], al[mi], bh);
                }
            }
        }
        __syncthreads();
    }
}

// ---------------------------------------------------------------------------
// Fused QKV projections. grid (32, 8, 3): z = which (0 Q, 1 K, 2 V), y = 2 heads.
// ---------------------------------------------------------------------------
__global__ __launch_bounds__(256) void qkv_kernel(
    const float* __restrict__ pre_q, const float* __restrict__ pre_k,
    const float* __restrict__ pre_v,
    const float* __restrict__ Wq, const float* __restrict__ bq,
    const float* __restrict__ Wk, const float* __restrict__ bk,
    const float* __restrict__ Wv, const float* __restrict__ bv)
{
    __shared__ __half Ah[128*40], Al[128*40], Bh[128*40], Bl[128*40];
    const int tid = threadIdx.x, lane = tid & 31, w = tid >> 5;
    const int wm = w >> 1, wn = w & 1, qid = lane >> 2, tq = lane & 3;
    const int which = blockIdx.z;
    const float* X    = which == 0 ? pre_q : which == 1 ? pre_k : pre_v;
    const float* W    = which == 0 ? Wq : which == 1 ? Wk : Wv;
    const float* bias = which == 0 ? bq : which == 1 ? bk : bv;
    const int mbase = blockIdx.x * 128, h0 = blockIdx.y * 2;

    float acc[2][8][4];
#pragma unroll
    for (int mi = 0; mi < 2; mi++)
#pragma unroll
        for (int ni = 0; ni < 8; ni++)
#pragma unroll
            for (int i = 0; i < 4; i++) acc[mi][ni][i] = 0.f;

    proj_mainloop(X + (size_t)mbase * kDM, W, 0, h0, Ah, Al, Bh, Bl,
                  acc, tid, wm, wn, qid, tq);

    const float qs = (which == 0) ? 0.125f : 1.f;
#pragma unroll
    for (int mi = 0; mi < 2; mi++)
#pragma unroll
        for (int ni = 0; ni < 8; ni++) {
            int r0 = mbase + wm*32 + mi*16 + qid;
            int d0 = wn*64 + ni*8 + tq*2;
            int head = h0 + (d0 >> 6), dd = d0 & 63;
            float bs0 = bias[head*kD + dd], bs1 = bias[head*kD + dd + 1];
#pragma unroll
            for (int hv = 0; hv < 2; hv++) {
                int r = r0 + hv*8, b = r >> 11, s = r & 2047;
                float v0 = acc[mi][ni][hv*2]     + bs0;
                float v1 = acc[mi][ni][hv*2 + 1] + bs1;
                if (which == 2) {
                    __half h0_,l0_,h1_,l1_; splitf(v0,h0_,l0_); splitf(v1,h1_,l1_);
                    size_t a0 = ((size_t)(b*kH + head)*kD + dd)*kS + s;
                    gVh[a0] = h0_; gVl[a0] = l0_;
                    gVh[a0 + kS] = h1_; gVl[a0 + kS] = l1_;
                } else {
                    v0 *= qs; v1 *= qs;
                    __half h0_,l0_,h1_,l1_; splitf(v0,h0_,l0_); splitf(v1,h1_,l1_);
                    size_t a0 = ((size_t)(b*kH + head)*kS + s)*kD + dd;
                    __half* Hh = (which == 0) ? gQh : gKh;
                    __half* Hl = (which == 0) ? gQl : gKl;
                    *reinterpret_cast<__half2*>(Hh + a0) = __halves2half2(h0_,h1_);
                    *reinterpret_cast<__half2*>(Hl + a0) = __halves2half2(l0_,l1_);
                }
            }
        }
}

// ---------------- attention gemms (16 warps: warp tile 32 rows x 16 cols) ----
DEVI void gemm_score(const __half* Qh, const __half* Ql,
                     const __half* Kh, const __half* Kl,
                     float cs[2][2][4], int wm, int wn, int qid, int tq) {
#pragma unroll
    for (int kf = 0; kf < 64; kf += 16) {
        uint32_t ah[2][4], al[2][4];
#pragma unroll
        for (int mi = 0; mi < 2; mi++) {
            int r = wm*32 + mi*16 + qid;
            load_a(Qh + r*72 + kf + tq*2, 72, ah[mi]);
            load_a(Ql + r*72 + kf + tq*2, 72, al[mi]);
        }
#pragma unroll
        for (int ni = 0; ni < 2; ni++) {
            int n = wn*16 + ni*8 + qid;
            uint32_t bh[2], bl[2];
            load_b(Kh + n*72 + kf + tq*2, bh);
            load_b(Kl + n*72 + kf + tq*2, bl);
#pragma unroll
            for (int mi = 0; mi < 2; mi++) {
                mma16816(cs[mi][ni], ah[mi], bh);
                mma16816(cs[mi][ni], ah[mi], bl);
                mma16816(cs[mi][ni], al[mi], bh);
            }
        }
    }
}
DEVI void gemm_pv(const __half* Ph, const __half* Vh, const __half* Vl,
                  float co[2][2][4], int wm, int wn, int qid, int tq) {
#pragma unroll
    for (int kf = 0; kf < 64; kf += 16) {
        uint32_t ah[2][4];
#pragma unroll
        for (int mi = 0; mi < 2; mi++) {
            int r = wm*32 + mi*16 + qid;
            load_a(Ph + r*72 + kf + tq*2, 72, ah[mi]);
        }
#pragma unroll
        for (int ni = 0; ni < 2; ni++) {
            int n = wn*16 + ni*8 + qid;
            uint32_t bh[2], bl[2];
            load_b(Vh + n*72 + kf + tq*2, bh);
            load_b(Vl + n*72 + kf + tq*2, bl);
#pragma unroll
            for (int mi = 0; mi < 2; mi++) {
                mma16816(co[mi][ni], ah[mi], bh);
                mma16816(co[mi][ni], ah[mi], bl);
            }
        }
    }
}

// ---------------------------------------------------------------------------
// Attention: 512 threads, single pass, unnormalized probs straight to gmem,
// double-buffered cp.async K/V, fp16-hi P@V. grid(16, 32), 132KB smem.
// ---------------------------------------------------------------------------
__global__ __launch_bounds__(512, 1) void attn_kernel(float* __restrict__ attnOut)
{
    extern __shared__ __align__(16) char sm[];
    __half* Qh = (__half*)sm;                 // 128x72 hi
    __half* Ql = (__half*)(sm + 18432);       // 128x72 lo
    // KV stage s at 36864 + s*36864: Kh,Kl,Vh,Vl each 64x72
    __half* Ph = (__half*)(sm + 110592);      // 128x72
    float* rps = (float*)(sm + 129024);       // 128x4
    float* rl  = (float*)(sm + 131072);       // 128
    float* rnv = (float*)(sm + 131584);       // 128

    const int tid = threadIdx.x, lane = tid & 31, w = tid >> 5;
    const int wm = w >> 2, wn = w & 3, qid = lane >> 2, tq = lane & 3;
    const int bh = blockIdx.y, b = bh >> 4, h = bh & 15;
    const int q0 = blockIdx.x * 128;
    const uint32_t sb = s2u(sm);

    if (tid < 128) rl[tid] = 0.f;
#pragma unroll
    for (int i = 0; i < 4; i++) {             // Q preload
        int idx = i*512 + tid, arr = idx >> 10, rem = idx & 1023;
        int r = rem >> 3, j = rem & 7;
        cpasync16(sb + arr*18432 + r*144 + j*16,
                  (arr ? gQl : gQh) + ((size_t)bh*kS + q0 + r)*kD + j*8);
    }
#pragma unroll
    for (int i = 0; i < 4; i++) {             // KV tile 0
        int idx = i*512 + tid, arr = idx >> 9, rem = idx & 511;
        int r = rem >> 3, j = rem & 7;
        const __half* src = arr == 0 ? gKh + ((size_t)bh*kS + r)*kD + j*8
                          : arr == 1 ? gKl + ((size_t)bh*kS + r)*kD + j*8
                          : arr == 2 ? gVh + ((size_t)bh*kD + r)*kS + j*8
                          :            gVl + ((size_t)bh*kD + r)*kS + j*8;
        cpasync16(sb + 36864 + arr*9216 + r*144 + j*16, src);
    }
    cpcommit();

    float co[2][2][4];
#pragma unroll
    for (int mi = 0; mi < 2; mi++)
#pragma unroll
        for (int ni = 0; ni < 2; ni++)
#pragma unroll
            for (int i = 0; i < 4; i++) co[mi][ni][i] = 0.f;

    for (int kt = 0; kt < 32; kt++) {
        const int cur = kt & 1;
        cpwait0();
        __syncthreads();
        if (kt + 1 < 32) {                    // prefetch next KV tile
            const int nxt = cur ^ 1, k1 = (kt + 1) * 64;
#pragma unroll
            for (int i = 0; i < 4; i++) {
                int idx = i*512 + tid, arr = idx >> 9, rem = idx & 511;
                int r = rem >> 3, j = rem & 7;
                const __half* src = arr == 0 ? gKh + ((size_t)bh*kS + k1 + r)*kD + j*8
                                  : arr == 1 ? gKl + ((size_t)bh*kS + k1 + r)*kD + j*8
                                  : arr == 2 ? gVh + ((size_t)bh*kD + r)*kS + k1 + j*8
                                  :            gVl + ((size_t)bh*kD + r)*kS + k1 + j*8;
                cpasync16(sb + 36864 + nxt*36864 + arr*9216 + r*144 + j*16, src);
            }
            cpcommit();
        }
        const __half* Kh = (const __half*)(sm + 36864 + cur*36864);
        const __half* Kl = Kh + 4608;
        const __half* Vh = Kl + 4608;
        const __half* Vl = Vh + 4608;

        float cs[2][2][4];
#pragma unroll
        for (int mi = 0; mi < 2; mi++)
#pragma unroll
            for (int ni = 0; ni < 2; ni++)
#pragma unroll
                for (int i = 0; i < 4; i++) cs[mi][ni][i] = 0.f;
        gemm_score(Qh, Ql, Kh, Kl, cs, wm, wn, qid, tq);

        // exp in regs -> Ph (fp16) + gmem probs (fp32, direct) + rowsum partials
#pragma unroll
        for (int mi = 0; mi < 2; mi++) {
            int ra = wm*32 + mi*16 + qid, rb = ra + 8;
            float pa = 0.f, pb = 0.f;
#pragma unroll
            for (int ni = 0; ni < 2; ni++) {
                int c = wn*16 + ni*8 + tq*2;
                float e0 = fexp(cs[mi][ni][0]), e1 = fexp(cs[mi][ni][1]);
                float e2 = fexp(cs[mi][ni][2]), e3 = fexp(cs[mi][ni][3]);
                pa += e0 + e1; pb += e2 + e3;
                *reinterpret_cast<__half2*>(Ph + ra*72 + c) =
                    __halves2half2(__float2half_rn(e0), __float2half_rn(e1));
                *reinterpret_cast<__half2*>(Ph + rb*72 + c) =
                    __halves2half2(__float2half_rn(e2), __float2half_rn(e3));
                size_t kb = ((size_t)h*kS + kt*64 + c)*kB + b;
                attnOut[kb*kS + q0 + ra]       = e0;
                attnOut[(kb + 2)*kS + q0 + ra] = e1;
                attnOut[kb*kS + q0 + rb]       = e2;
                attnOut[(kb + 2)*kS + q0 + rb] = e3;
            }
            pa += __shfl_xor_sync(0xffffffffu, pa, 1);
            pa += __shfl_xor_sync(0xffffffffu, pa, 2);
            pb += __shfl_xor_sync(0xffffffffu, pb, 1);
            pb += __shfl_xor_sync(0xffffffffu, pb, 2);
            if (tq == 0) { rps[ra*4 + wn] = pa; rps[rb*4 + wn] = pb; }
        }
        __syncthreads();
        if (tid < 128)
            rl[tid] += rps[tid*4] + rps[tid*4+1] + rps[tid*4+2] + rps[tid*4+3];
        gemm_pv(Ph, Vh, Vl, co, wm, wn, qid, tq);
    }
    __syncthreads();
    if (tid < 128) {
        float inv = 1.f / rl[tid];
        rnv[tid] = inv;
        g_rinv[(size_t)bh*kS + q0 + tid] = inv;
    }
    __syncthreads();
#pragma unroll
    for (int mi = 0; mi < 2; mi++)
#pragma unroll
        for (int ni = 0; ni < 2; ni++) {
            int r = wm*32 + mi*16 + qid, d0 = wn*16 + ni*8 + tq*2;
            float i0 = rnv[r], i1 = rnv[r + 8];
            size_t a0 = ((size_t)(b*kS + q0 + r))*kDM + h*kD + d0;
            size_t a1 = a0 + (size_t)8*kDM;
            g_C[a0] = co[mi][ni][0]*i0; g_C[a0 + 1] = co[mi][ni][1]*i0;
            g_C[a1] = co[mi][ni][2]*i1; g_C[a1 + 1] = co[mi][ni][3]*i1;
        }
}

// ---------------------------------------------------------------------------
// Tail: blocks [0,256) = out-projection (g_C @ Wo + bo); blocks [256,33024) =
// attn rescale (DRAM-bound) — overlapped in one launch.
// ---------------------------------------------------------------------------
__global__ __launch_bounds__(256) void tail_kernel(
    const float* __restrict__ Wo, const float* __restrict__ bo,
    float* __restrict__ out, float* __restrict__ attn)
{
    __shared__ __half Ah[128*40], Al[128*40], Bh[128*40], Bl[128*40];
    const int tid = threadIdx.x;
    if (blockIdx.x >= 256) {                  // rescale: 16 floats/thread
        size_t rb = blockIdx.x - 256;
        size_t base = (rb * 256 + tid) * 16;
        int q = (int)(base & 2047);
        int b = (int)((base >> 11) & 1);
        int h = (int)(base >> 23);
        const float* rv = g_rinv + ((size_t)(b*kH + h))*kS + q;
#pragma unroll
        for (int i = 0; i < 4; i++) {
            float4 r4 = *reinterpret_cast<const float4*>(rv + i*4);
            float4 v  = *reinterpret_cast<float4*>(attn + base + i*4);
            v.x *= r4.x; v.y *= r4.y; v.z *= r4.z; v.w *= r4.w;
            *reinterpret_cast<float4*>(attn + base + i*4) = v;
        }
        return;
    }
    const int lane = tid & 31, w = tid >> 5;
    const int wm = w >> 1, wn = w & 1, qid = lane >> 2, tq = lane & 3;
    const int mbase = (blockIdx.x & 31) * 128, col0 = (blockIdx.x >> 5) * 128;

    float acc[2][8][4];
#pragma unroll
    for (int mi = 0; mi < 2; mi++)
#pragma unroll
        for (int ni = 0; ni < 8; ni++)
#pragma unroll
            for (int i = 0; i < 4; i++) acc[mi][ni][i] = 0.f;

    proj_mainloop(g_C + (size_t)mbase * kDM, Wo, 1, col0, Ah, Al, Bh, Bl,
                  acc, tid, wm, wn, qid, tq);
#pragma unroll
    for (int mi = 0; mi < 2; mi++)
#pragma unroll
        for (int ni = 0; ni < 8; ni++) {
            int r0 = mbase + wm*32 + mi*16 + qid;
            int d0 = wn*64 + ni*8 + tq*2;
            float bs0 = bo[col0 + d0], bs1 = bo[col0 + d0 + 1];
#pragma unroll
            for (int hv = 0; hv < 2; hv++) {
                int r = r0 + hv*8;
                out[(size_t)r*kDM + col0 + d0]     = acc[mi][ni][hv*2]     + bs0;
                out[(size_t)r*kDM + col0 + d0 + 1] = acc[mi][ni][hv*2 + 1] + bs1;
            }
        }
}

// ---------------------------------------------------------------------------
extern "C" void kernel_launch(void* const* d_in, const int* in_sizes, int n_in,
                              void* d_out, int out_size) {
    const float* pre_q = (const float*)d_in[0];
    const float* pre_k = (const float*)d_in[1];
    const float* pre_v = (const float*)d_in[2];
    const float* Wq = (const float*)d_in[4];
    const float* bq = (const float*)d_in[5];
    const float* Wk = (const float*)d_in[6];
    const float* bk = (const float*)d_in[7];
    const float* Wv = (const float*)d_in[8];
    const float* bv = (const float*)d_in[9];
    const float* Wo = (const float*)d_in[10];
    const float* bo = (const float*)d_in[11];

    float* out  = (float*)d_out;
    float* attn = out + (size_t)kB * kS * kDM;

    cudaFuncSetAttribute(attn_kernel,
                         cudaFuncAttributeMaxDynamicSharedMemorySize, ATTN_SMEM);

    qkv_kernel<<<dim3(32, 8, 3), 256>>>(pre_q, pre_k, pre_v,
                                        Wq, bq, Wk, bk, Wv, bv);
    attn_kernel<<<dim3(16, 32), 512, ATTN_SMEM>>>(attn);
    tail_kernel<<<256 + 32768, 256>>>(Wo, bo, out, attn);
}

// round 6
// speedup vs baseline: 1.1440x; 1.1440x over previous
#include <cuda_runtime.h>
#include <cuda_fp16.h>
#include <stdint.h>

#define DEVI __device__ __forceinline__

namespace {
constexpr int kB = 2, kS = 2048, kDM = 1024, kH = 16, kD = 64;
constexpr int kBS = kB * kS, kBH = kB * kH;
constexpr int ATTN_SMEM = 164352;
constexpr int PROJ_SMEM = 81920;
}

// ---------------- static scratch ----------------
__device__ __half gXh[(size_t)3*kBS*kDM], gXl[(size_t)3*kBS*kDM]; // [which][r][k]
__device__ __half gWh[(size_t)64*64*kDM], gWl[(size_t)64*64*kDM]; // [w64][d][k] (48.. = Wo)
__device__ __half gQh[(size_t)kBH*kS*kD], gQl[(size_t)kBH*kS*kD]; // [bh][s][d] (x0.125)
__device__ __half gKh[(size_t)kBH*kS*kD], gKl[(size_t)kBH*kS*kD]; // [bh][s][d]
__device__ __half gVh[(size_t)kBH*kD*kS], gVl[(size_t)kBH*kD*kS]; // [bh][d][s]
__device__ __half gCh[(size_t)kBS*kDM],  gCl[(size_t)kBS*kDM];    // concat O (split)

// ---------------- helpers ----------------
DEVI void mma16816(float c[4], const uint32_t a[4], const uint32_t b[2]) {
    asm volatile(
        "mma.sync.aligned.m16n8k16.row.col.f32.f16.f16.f32 "
        "{%0,%1,%2,%3}, {%4,%5,%6,%7}, {%8,%9}, {%0,%1,%2,%3};\n"
        : "+f"(c[0]), "+f"(c[1]), "+f"(c[2]), "+f"(c[3])
        : "r"(a[0]), "r"(a[1]), "r"(a[2]), "r"(a[3]), "r"(b[0]), "r"(b[1]));
}
DEVI void splitf(float x, __half& hi, __half& lo) {
    hi = __float2half_rn(x);
    lo = __float2half_rn(x - __half2float(hi));
}
DEVI void load_a(const __half* base, int st, uint32_t a[4]) {
    a[0] = *reinterpret_cast<const uint32_t*>(base);
    a[1] = *reinterpret_cast<const uint32_t*>(base + 8 * st);
    a[2] = *reinterpret_cast<const uint32_t*>(base + 8);
    a[3] = *reinterpret_cast<const uint32_t*>(base + 8 * st + 8);
}
DEVI void load_b(const __half* base, uint32_t b[2]) {
    b[0] = *reinterpret_cast<const uint32_t*>(base);
    b[1] = *reinterpret_cast<const uint32_t*>(base + 8);
}
DEVI float fexp(float x) {   // FFMA-only exp, |rel err| ~1e-7
    float t = x * 1.44269504f;
    float fn = rintf(t);
    float f = t - fn;
    float p = 1.33336498e-3f;
    p = fmaf(p, f, 9.61793093e-3f);
    p = fmaf(p, f, 5.55043924e-2f);
    p = fmaf(p, f, 2.40226507e-1f);
    p = fmaf(p, f, 6.93147182e-1f);
    p = fmaf(p, f, 1.0f);
    return __int_as_float(__float_as_int(p) + (((int)fn) << 23));
}
DEVI void cpasync16(uint32_t dst, const void* src) {
    asm volatile("cp.async.cg.shared.global [%0], [%1], 16;\n" :: "r"(dst), "l"(src));
}
DEVI void cpcommit() { asm volatile("cp.async.commit_group;\n" ::: "memory"); }
DEVI void cpwait0()  { asm volatile("cp.async.wait_group 0;\n" ::: "memory"); }
DEVI uint32_t s2u(const void* p) {
    uint32_t a;
    asm("{ .reg .u64 t; cvta.to.shared.u64 t, %1; cvt.u32.u64 %0, t; }" : "=r"(a) : "l"(p));
    return a;
}

// ---------------------------------------------------------------------------
// Pre-split X: fp32 -> hi/lo halves (pure DRAM). grid (4096, 3), 256 thr.
// ---------------------------------------------------------------------------
__global__ __launch_bounds__(256) void presplit_x(
    const float* __restrict__ pre_q, const float* __restrict__ pre_k,
    const float* __restrict__ pre_v)
{
    const int which = blockIdx.y;
    const float* X = which == 0 ? pre_q : which == 1 ? pre_k : pre_v;
    size_t i4 = (size_t)blockIdx.x * 256 + threadIdx.x;
    float4 v = reinterpret_cast<const float4*>(X)[i4];
    size_t o = (size_t)which * 4194304 + i4 * 4;
    __half h0,h1,h2,h3,l0,l1,l2,l3;
    splitf(v.x,h0,l0); splitf(v.y,h1,l1); splitf(v.z,h2,l2); splitf(v.w,h3,l3);
    *reinterpret_cast<__half2*>(gXh + o)     = __halves2half2(h0,h1);
    *reinterpret_cast<__half2*>(gXh + o + 2) = __halves2half2(h2,h3);
    *reinterpret_cast<__half2*>(gXl + o)     = __halves2half2(l0,l1);
    *reinterpret_cast<__half2*>(gXl + o + 2) = __halves2half2(l2,l3);
}

// ---------------------------------------------------------------------------
// Pre-split + transpose W -> [w64][d][k] halves. grid (16, 64), 256 thr.
// w64<48: which=w64>>4, head=w64&15 (W [h][k][64]); w64>=48: Wo col-block.
// ---------------------------------------------------------------------------
__global__ __launch_bounds__(256) void presplit_w(
    const float* __restrict__ Wq, const float* __restrict__ Wk,
    const float* __restrict__ Wv, const float* __restrict__ Wo)
{
    __shared__ float tile[64][65];
    const int tid = threadIdx.x;
    const int w64 = blockIdx.y, k0 = blockIdx.x * 64;
    const float* src; int ld;
    if (w64 < 48) {
        int which = w64 >> 4, h = w64 & 15;
        src = (which == 0 ? Wq : which == 1 ? Wk : Wv) + (size_t)h * kDM * 64;
        ld = 64;
    } else {
        src = Wo + (w64 - 48) * 64;
        ld = 1024;
    }
#pragma unroll
    for (int p = 0; p < 4; p++) {
        int rr = p * 16 + (tid >> 4), c4 = (tid & 15) * 4;
        float4 v = *reinterpret_cast<const float4*>(src + (size_t)(k0 + rr) * ld + c4);
        tile[c4][rr] = v.x; tile[c4+1][rr] = v.y;
        tile[c4+2][rr] = v.z; tile[c4+3][rr] = v.w;
    }
    __syncthreads();
    int d = tid >> 2, kk0 = (tid & 3) * 16;
    size_t base = ((size_t)w64 * 64 + d) * kDM + k0 + kk0;
#pragma unroll
    for (int j = 0; j < 16; j += 2) {
        __half ha,la,hb,lb;
        splitf(tile[d][kk0 + j],     ha, la);
        splitf(tile[d][kk0 + j + 1], hb, lb);
        *reinterpret_cast<__half2*>(gWh + base + j) = __halves2half2(ha, hb);
        *reinterpret_cast<__half2*>(gWl + base + j) = __halves2half2(la, lb);
    }
}

// ---------------------------------------------------------------------------
// cp.async double-buffered 128x128 GEMM mainloop (K=1024, 3-term split).
// A rows at Asrc (+row*1024), B rows at Bsrc (+n*1024). acc[2][8][4].
// ---------------------------------------------------------------------------
DEVI void proj_mainloop(const __half* Ah_s, const __half* Al_s,
                        const __half* Bh_s, const __half* Bl_s,
                        char* sm, uint32_t sb, float acc[2][8][4],
                        int tid, int wm, int wn, int qid, int tq)
{
#pragma unroll 1
    for (int kc = -1; kc < 32; kc++) {
        if (kc >= 0) {
            cpwait0();
            __syncthreads();
        }
        if (kc + 1 < 32) {              // issue stage kc+1
            const int stg = (kc + 1) & 1, k0 = (kc + 1) * 32;
#pragma unroll
            for (int i = 0; i < 8; i++) {
                int idx = i * 256 + tid;
                int arr = idx >> 9, rem = idx & 511;
                int r = rem >> 2, ch = rem & 3;
                const __half* s = arr == 0 ? Ah_s : arr == 1 ? Al_s
                                : arr == 2 ? Bh_s : Bl_s;
                cpasync16(sb + stg*40960 + arr*10240 + r*80 + ch*16,
                          s + (size_t)r * kDM + k0 + ch*8);
            }
            cpcommit();
        }
        if (kc < 0) continue;
        const __half* Ah = reinterpret_cast<const __half*>(sm + (kc & 1) * 40960);
        const __half* Al = Ah + 5120;
        const __half* Bh = Al + 5120;
        const __half* Bl = Bh + 5120;
#pragma unroll
        for (int ks = 0; ks < 2; ks++) {
            const int kf = ks * 16;
            uint32_t ahf[2][4], alf[2][4];
#pragma unroll
            for (int mi = 0; mi < 2; mi++) {
                int r = wm*32 + mi*16 + qid;
                load_a(Ah + r*40 + kf + tq*2, 40, ahf[mi]);
                load_a(Al + r*40 + kf + tq*2, 40, alf[mi]);
            }
#pragma unroll
            for (int ni = 0; ni < 8; ni++) {
                int n = wn*64 + ni*8 + qid;
                uint32_t bhf[2], blf[2];
                load_b(Bh + n*40 + kf + tq*2, bhf);
                load_b(Bl + n*40 + kf + tq*2, blf);
#pragma unroll
                for (int mi = 0; mi < 2; mi++) {
                    mma16816(acc[mi][ni], ahf[mi], bhf);
                    mma16816(acc[mi][ni], ahf[mi], blf);
                    mma16816(acc[mi][ni], alf[mi], bhf);
                }
            }
        }
    }
}

// ---------------------------------------------------------------------------
// QKV projections. grid (32, 8, 3): z = which, y = 2 heads. 256 thr.
// ---------------------------------------------------------------------------
__global__ __launch_bounds__(256) void qkv_kernel(
    const float* __restrict__ bq, const float* __restrict__ bk,
    const float* __restrict__ bv)
{
    extern __shared__ __align__(16) char sm[];
    const int tid = threadIdx.x, lane = tid & 31, w = tid >> 5;
    const int wm = w >> 1, wn = w & 1, qid = lane >> 2, tq = lane & 3;
    const int which = blockIdx.z, mbase = blockIdx.x * 128, h0 = blockIdx.y * 2;
    const float* bias = which == 0 ? bq : which == 1 ? bk : bv;

    float acc[2][8][4];
#pragma unroll
    for (int mi = 0; mi < 2; mi++)
#pragma unroll
        for (int ni = 0; ni < 8; ni++)
#pragma unroll
            for (int i = 0; i < 4; i++) acc[mi][ni][i] = 0.f;

    size_t aoff = (size_t)which * 4194304 + (size_t)mbase * kDM;
    size_t boff = ((size_t)(which*16 + h0) * 64) * kDM;
    proj_mainloop(gXh + aoff, gXl + aoff, gWh + boff, gWl + boff,
                  sm, s2u(sm), acc, tid, wm, wn, qid, tq);

    const float qs = (which == 0) ? 0.125f : 1.f;
#pragma unroll
    for (int mi = 0; mi < 2; mi++)
#pragma unroll
        for (int ni = 0; ni < 8; ni++) {
            int r0 = mbase + wm*32 + mi*16 + qid;
            int d0 = wn*64 + ni*8 + tq*2;
            int head = h0 + (d0 >> 6), dd = d0 & 63;
            float bs0 = bias[head*kD + dd], bs1 = bias[head*kD + dd + 1];
#pragma unroll
            for (int hv = 0; hv < 2; hv++) {
                int r = r0 + hv*8, b = r >> 11, s = r & 2047;
                float v0 = acc[mi][ni][hv*2]     + bs0;
                float v1 = acc[mi][ni][hv*2 + 1] + bs1;
                if (which == 2) {
                    __half h0_,l0_,h1_,l1_; splitf(v0,h0_,l0_); splitf(v1,h1_,l1_);
                    size_t a0 = ((size_t)(b*kH + head)*kD + dd)*kS + s;
                    gVh[a0] = h0_; gVl[a0] = l0_;
                    gVh[a0 + kS] = h1_; gVl[a0 + kS] = l1_;
                } else {
                    v0 *= qs; v1 *= qs;
                    __half h0_,l0_,h1_,l1_; splitf(v0,h0_,l0_); splitf(v1,h1_,l1_);
                    size_t a0 = ((size_t)(b*kH + head)*kS + s)*kD + dd;
                    __half* Hh = (which == 0) ? gQh : gKh;
                    __half* Hl = (which == 0) ? gQl : gKl;
                    *reinterpret_cast<__half2*>(Hh + a0) = __halves2half2(h0_,h1_);
                    *reinterpret_cast<__half2*>(Hl + a0) = __halves2half2(l0_,l1_);
                }
            }
        }
}

// ---------------------------------------------------------------------------
// Out-projection. grid (32, 8), 256 thr. A = gC split, B = Wo blocks (w64>=48).
// ---------------------------------------------------------------------------
__global__ __launch_bounds__(256) void outproj_kernel(
    const float* __restrict__ bo, float* __restrict__ out)
{
    extern __shared__ __align__(16) char sm[];
    const int tid = threadIdx.x, lane = tid & 31, w = tid >> 5;
    const int wm = w >> 1, wn = w & 1, qid = lane >> 2, tq = lane & 3;
    const int mbase = blockIdx.x * 128, col0 = blockIdx.y * 128;

    float acc[2][8][4];
#pragma unroll
    for (int mi = 0; mi < 2; mi++)
#pragma unroll
        for (int ni = 0; ni < 8; ni++)
#pragma unroll
            for (int i = 0; i < 4; i++) acc[mi][ni][i] = 0.f;

    size_t aoff = (size_t)mbase * kDM;
    size_t boff = ((size_t)(48*64 + col0)) * kDM;
    proj_mainloop(gCh + aoff, gCl + aoff, gWh + boff, gWl + boff,
                  sm, s2u(sm), acc, tid, wm, wn, qid, tq);
#pragma unroll
    for (int mi = 0; mi < 2; mi++)
#pragma unroll
        for (int ni = 0; ni < 8; ni++) {
            int r0 = mbase + wm*32 + mi*16 + qid;
            int d0 = wn*64 + ni*8 + tq*2;
            float bs0 = bo[col0 + d0], bs1 = bo[col0 + d0 + 1];
#pragma unroll
            for (int hv = 0; hv < 2; hv++) {
                int r = r0 + hv*8;
                out[(size_t)r*kDM + col0 + d0]     = acc[mi][ni][hv*2]     + bs0;
                out[(size_t)r*kDM + col0 + d0 + 1] = acc[mi][ni][hv*2 + 1] + bs1;
            }
        }
}

// ---------------- attention gemms (8 warps, warp tile 32x32) ----------------
DEVI void gemm_score3(const __half* Qh, const __half* Ql,
                      const __half* Kh, const __half* Kl,
                      float cs[2][4][4], int wm, int wn, int qid, int tq) {
#pragma unroll
    for (int kf = 0; kf < 64; kf += 16) {
        uint32_t ah[2][4], al[2][4];
#pragma unroll
        for (int mi = 0; mi < 2; mi++) {
            int r = wm*32 + mi*16 + qid;
            load_a(Qh + r*72 + kf + tq*2, 72, ah[mi]);
            load_a(Ql + r*72 + kf + tq*2, 72, al[mi]);
        }
#pragma unroll
        for (int ni = 0; ni < 4; ni++) {
            int n = wn*32 + ni*8 + qid;
            uint32_t bh[2], bl[2];
            load_b(Kh + n*72 + kf + tq*2, bh);
            load_b(Kl + n*72 + kf + tq*2, bl);
#pragma unroll
            for (int mi = 0; mi < 2; mi++) {
                mma16816(cs[mi][ni], ah[mi], bh);
                mma16816(cs[mi][ni], ah[mi], bl);
                mma16816(cs[mi][ni], al[mi], bh);
            }
        }
    }
}
DEVI void gemm_pv2(const __half* Ph, const __half* Vh, const __half* Vl,
                   float co[2][4][4], int wm, int wn, int qid, int tq) {
#pragma unroll
    for (int kf = 0; kf < 64; kf += 16) {
        uint32_t pa[2][4];
#pragma unroll
        for (int mi = 0; mi < 2; mi++) {
            int r = wm*32 + mi*16 + qid;
            load_a(Ph + r*72 + kf + tq*2, 72, pa[mi]);
        }
#pragma unroll
        for (int ni = 0; ni < 4; ni++) {
            int n = wn*32 + ni*8 + qid;
            uint32_t bh[2], bl[2];
            load_b(Vh + n*72 + kf + tq*2, bh);
            load_b(Vl + n*72 + kf + tq*2, bl);
#pragma unroll
            for (int mi = 0; mi < 2; mi++) {
                mma16816(co[mi][ni], pa[mi], bh);
                mma16816(co[mi][ni], pa[mi], bl);
            }
        }
    }
}

// ---------------------------------------------------------------------------
// Attention (R4 structure): 256 thr, single pass, unnormalized probs via Ssm
// (coalesced gmem writes), 2-term P@V, rescale folded into epilogue.
// grid(16, 32), 164KB smem.
// ---------------------------------------------------------------------------
__global__ __launch_bounds__(256, 1) void attn_kernel(float* __restrict__ attnOut)
{
    extern __shared__ __align__(16) char sm[];
    __half* Qh = (__half*)sm;                   // 128x72
    __half* Ql = (__half*)(sm + 18432);
    // KV stage s at 36864 + s*36864: Kh,Kl,Vh,Vl each 64x72
    __half* Ph = (__half*)(sm + 110592);        // 128x72
    float* Ssm = (float*)(sm + 129024);         // 128x65
    float* rps = (float*)(sm + 162304);         // 128x2
    float* rl  = (float*)(sm + 163328);         // 128
    float* rnv = (float*)(sm + 163840);         // 128

    const int tid = threadIdx.x, lane = tid & 31, w = tid >> 5;
    const int wm = w >> 1, wn = w & 1, qid = lane >> 2, tq = lane & 3;
    const int bh = blockIdx.y, b = bh >> 4, h = bh & 15;
    const int q0 = blockIdx.x * 128;
    const uint32_t sb = s2u(sm);

    if (tid < 128) rl[tid] = 0.f;
#pragma unroll
    for (int i = 0; i < 8; i++) {               // Q preload
        int arr = i >> 2, wv = ((i & 3) << 8) + tid;
        int r = wv >> 3, j = wv & 7;
        cpasync16(sb + arr*18432 + r*144 + j*16,
                  (arr ? gQl : gQh) + ((size_t)bh*kS + q0 + r)*kD + j*8);
    }
#pragma unroll
    for (int i = 0; i < 8; i++) {               // KV tile 0
        int arr = i >> 1, wv = ((i & 1) << 8) + tid;
        int r = wv >> 3, j = wv & 7;
        const __half* src = arr == 0 ? gKh + ((size_t)bh*kS + r)*kD + j*8
                          : arr == 1 ? gKl + ((size_t)bh*kS + r)*kD + j*8
                          : arr == 2 ? gVh + ((size_t)bh*kD + r)*kS + j*8
                          :            gVl + ((size_t)bh*kD + r)*kS + j*8;
        cpasync16(sb + 36864 + arr*9216 + r*144 + j*16, src);
    }
    cpcommit();

    float co[2][4][4];
#pragma unroll
    for (int mi = 0; mi < 2; mi++)
#pragma unroll
        for (int ni = 0; ni < 4; ni++)
#pragma unroll
            for (int i = 0; i < 4; i++) co[mi][ni][i] = 0.f;

    for (int kt = 0; kt < 32; kt++) {
        const int cur = kt & 1;
        cpwait0();
        __syncthreads();
        if (kt + 1 < 32) {                      // prefetch next KV tile
            const int nxt = cur ^ 1, k1 = (kt + 1) * 64;
#pragma unroll
            for (int i = 0; i < 8; i++) {
                int arr = i >> 1, wv = ((i & 1) << 8) + tid;
                int r = wv >> 3, j = wv & 7;
                const __half* src = arr == 0 ? gKh + ((size_t)bh*kS + k1 + r)*kD + j*8
                                  : arr == 1 ? gKl + ((size_t)bh*kS + k1 + r)*kD + j*8
                                  : arr == 2 ? gVh + ((size_t)bh*kD + r)*kS + k1 + j*8
                                  :            gVl + ((size_t)bh*kD + r)*kS + k1 + j*8;
                cpasync16(sb + 36864 + nxt*36864 + arr*9216 + r*144 + j*16, src);
            }
            cpcommit();
        }
        const __half* Kh = (const __half*)(sm + 36864 + cur*36864);
        const __half* Kl = Kh + 4608;
        const __half* Vh = Kl + 4608;
        const __half* Vl = Vh + 4608;

        float cs[2][4][4];
#pragma unroll
        for (int mi = 0; mi < 2; mi++)
#pragma unroll
            for (int ni = 0; ni < 4; ni++)
#pragma unroll
                for (int i = 0; i < 4; i++) cs[mi][ni][i] = 0.f;
        gemm_score3(Qh, Ql, Kh, Kl, cs, wm, wn, qid, tq);

        // exp in regs -> Ssm (fp32) + Ph (fp16) + rowsum partials
#pragma unroll
        for (int mi = 0; mi < 2; mi++) {
            int ra = wm*32 + mi*16 + qid, rb = ra + 8;
            float pa = 0.f, pb = 0.f;
#pragma unroll
            for (int ni = 0; ni < 4; ni++) {
                int c = wn*32 + ni*8 + tq*2;
                float e0 = fexp(cs[mi][ni][0]), e1 = fexp(cs[mi][ni][1]);
                float e2 = fexp(cs[mi][ni][2]), e3 = fexp(cs[mi][ni][3]);
                Ssm[ra*65 + c] = e0; Ssm[ra*65 + c + 1] = e1;
                Ssm[rb*65 + c] = e2; Ssm[rb*65 + c + 1] = e3;
                *reinterpret_cast<__half2*>(Ph + ra*72 + c) =
                    __halves2half2(__float2half_rn(e0), __float2half_rn(e1));
                *reinterpret_cast<__half2*>(Ph + rb*72 + c) =
                    __halves2half2(__float2half_rn(e2), __float2half_rn(e3));
                pa += e0 + e1; pb += e2 + e3;
            }
            pa += __shfl_xor_sync(0xffffffffu, pa, 1);
            pa += __shfl_xor_sync(0xffffffffu, pa, 2);
            pb += __shfl_xor_sync(0xffffffffu, pb, 1);
            pb += __shfl_xor_sync(0xffffffffu, pb, 2);
            if (tq == 0) { rps[ra*2 + wn] = pa; rps[rb*2 + wn] = pb; }
        }
        __syncthreads();
        if (tid < 128) rl[tid] += rps[tid*2] + rps[tid*2 + 1];

        // unnormalized probs attn[h, kg, b, q] (coalesced in q)
#pragma unroll
        for (int i = 0; i < 32; i++) {
            int kk = i*2 + (tid >> 7);
            int q  = tid & 127;
            attnOut[(((size_t)h*kS + kt*64 + kk)*kB + b)*kS + q0 + q] = Ssm[q*65 + kk];
        }
        gemm_pv2(Ph, Vh, Vl, co, wm, wn, qid, tq);
    }
    __syncthreads();
    if (tid < 128) rnv[tid] = 1.f / rl[tid];
    __syncthreads();

    // O epilogue: normalized, pre-split -> gCh/gCl
#pragma unroll
    for (int mi = 0; mi < 2; mi++)
#pragma unroll
        for (int ni = 0; ni < 4; ni++) {
            int r = wm*32 + mi*16 + qid, d0 = wn*32 + ni*8 + tq*2;
            float i0 = rnv[r], i1 = rnv[r + 8];
            float o0 = co[mi][ni][0]*i0, o1 = co[mi][ni][1]*i0;
            float o2 = co[mi][ni][2]*i1, o3 = co[mi][ni][3]*i1;
            __half h0_,l0_,h1_,l1_,h2_,l2_,h3_,l3_;
            splitf(o0,h0_,l0_); splitf(o1,h1_,l1_);
            splitf(o2,h2_,l2_); splitf(o3,h3_,l3_);
            size_t a0 = ((size_t)(b*kS + q0 + r))*kDM + h*kD + d0;
            size_t a1 = a0 + (size_t)8*kDM;
            *reinterpret_cast<__half2*>(gCh + a0) = __halves2half2(h0_,h1_);
            *reinterpret_cast<__half2*>(gCl + a0) = __halves2half2(l0_,l1_);
            *reinterpret_cast<__half2*>(gCh + a1) = __halves2half2(h2_,h3_);
            *reinterpret_cast<__half2*>(gCl + a1) = __halves2half2(l2_,l3_);
        }

    // rescale own attn slice (128 q x 2048 k), overlapped across waves
    for (int i = tid; i < 65536; i += 256) {
        int k = i >> 5, qq4 = (i & 31) * 4;
        size_t addr = (((size_t)h*kS + k)*kB + b)*kS + q0 + qq4;
        float4 rv = *reinterpret_cast<const float4*>(rnv + qq4);
        float4 v  = *reinterpret_cast<float4*>(attnOut + addr);
        v.x *= rv.x; v.y *= rv.y; v.z *= rv.z; v.w *= rv.w;
        *reinterpret_cast<float4*>(attnOut + addr) = v;
    }
}

// ---------------------------------------------------------------------------
extern "C" void kernel_launch(void* const* d_in, const int* in_sizes, int n_in,
                              void* d_out, int out_size) {
    const float* pre_q = (const float*)d_in[0];
    const float* pre_k = (const float*)d_in[1];
    const float* pre_v = (const float*)d_in[2];
    const float* Wq = (const float*)d_in[4];
    const float* bq = (const float*)d_in[5];
    const float* Wk = (const float*)d_in[6];
    const float* bk = (const float*)d_in[7];
    const float* Wv = (const float*)d_in[8];
    const float* bv = (const float*)d_in[9];
    const float* Wo = (const float*)d_in[10];
    const float* bo = (const float*)d_in[11];

    float* out  = (float*)d_out;
    float* attn = out + (size_t)kB * kS * kDM;

    cudaFuncSetAttribute(attn_kernel,
                         cudaFuncAttributeMaxDynamicSharedMemorySize, ATTN_SMEM);
    cudaFuncSetAttribute(qkv_kernel,
                         cudaFuncAttributeMaxDynamicSharedMemorySize, PROJ_SMEM);
    cudaFuncSetAttribute(outproj_kernel,
                         cudaFuncAttributeMaxDynamicSharedMemorySize, PROJ_SMEM);

    presplit_x<<<dim3(4096, 3), 256>>>(pre_q, pre_k, pre_v);
    presplit_w<<<dim3(16, 64), 256>>>(Wq, Wk, Wv, Wo);
    qkv_kernel<<<dim3(32, 8, 3), 256, PROJ_SMEM>>>(bq, bk, bv);
    attn_kernel<<<dim3(16, 32), 256, ATTN_SMEM>>>(attn);
    outproj_kernel<<<dim3(32, 8), 256, PROJ_SMEM>>>(bo, out);
}

// round 12
// speedup vs baseline: 1.5287x; 1.3363x over previous
#include <cuda_runtime.h>
#include <cuda_fp16.h>
#include <stdint.h>

#define DEVI __device__ __forceinline__

namespace {
constexpr int kB = 2, kS = 2048, kDM = 1024, kH = 16, kD = 64;
constexpr int kBS = kB * kS, kBH = kB * kH;
constexpr int ATTN_SMEM = 164352;
constexpr int PROJ_SMEM = 81920;
}

// ---------------- static scratch ----------------
__device__ __half gXh[(size_t)3*kBS*kDM], gXl[(size_t)3*kBS*kDM]; // [which][r][k]
__device__ __half gWh[(size_t)64*64*kDM], gWl[(size_t)64*64*kDM]; // [w64][d][k] (48.. = Wo)
__device__ __half gQh[(size_t)kBH*kS*kD], gQl[(size_t)kBH*kS*kD]; // [bh][s][d] (x0.125)
__device__ __half gKh[(size_t)kBH*kS*kD], gKl[(size_t)kBH*kS*kD]; // [bh][s][d]
__device__ __half gVh[(size_t)kBH*kD*kS], gVl[(size_t)kBH*kD*kS]; // [bh][d][s]
__device__ __half gCh[(size_t)kBS*kDM],  gCl[(size_t)kBS*kDM];    // concat O (split)
__device__ float  g_rinv[(size_t)kBH*kS];                         // 1/rowsum

// ---------------- helpers ----------------
DEVI void mma16816(float c[4], const uint32_t a[4], const uint32_t b[2]) {
    asm volatile(
        "mma.sync.aligned.m16n8k16.row.col.f32.f16.f16.f32 "
        "{%0,%1,%2,%3}, {%4,%5,%6,%7}, {%8,%9}, {%0,%1,%2,%3};\n"
        : "+f"(c[0]), "+f"(c[1]), "+f"(c[2]), "+f"(c[3])
        : "r"(a[0]), "r"(a[1]), "r"(a[2]), "r"(a[3]), "r"(b[0]), "r"(b[1]));
}
DEVI void splitf(float x, __half& hi, __half& lo) {
    hi = __float2half_rn(x);
    lo = __float2half_rn(x - __half2float(hi));
}
DEVI void load_a(const __half* base, int st, uint32_t a[4]) {
    a[0] = *reinterpret_cast<const uint32_t*>(base);
    a[1] = *reinterpret_cast<const uint32_t*>(base + 8 * st);
    a[2] = *reinterpret_cast<const uint32_t*>(base + 8);
    a[3] = *reinterpret_cast<const uint32_t*>(base + 8 * st + 8);
}
DEVI void load_b(const __half* base, uint32_t b[2]) {
    b[0] = *reinterpret_cast<const uint32_t*>(base);
    b[1] = *reinterpret_cast<const uint32_t*>(base + 8);
}
DEVI float fexp(float x) {   // FFMA-only exp, |rel err| ~1e-7
    float t = x * 1.44269504f;
    float fn = rintf(t);
    float f = t - fn;
    float p = 1.33336498e-3f;
    p = fmaf(p, f, 9.61793093e-3f);
    p = fmaf(p, f, 5.55043924e-2f);
    p = fmaf(p, f, 2.40226507e-1f);
    p = fmaf(p, f, 6.93147182e-1f);
    p = fmaf(p, f, 1.0f);
    return __int_as_float(__float_as_int(p) + (((int)fn) << 23));
}
DEVI void cpasync16(uint32_t dst, const void* src) {
    asm volatile("cp.async.cg.shared.global [%0], [%1], 16;\n" :: "r"(dst), "l"(src));
}
DEVI void cpcommit() { asm volatile("cp.async.commit_group;\n" ::: "memory"); }
DEVI void cpwait0()  { asm volatile("cp.async.wait_group 0;\n" ::: "memory"); }
DEVI uint32_t s2u(const void* p) {
    uint32_t a;
    asm("{ .reg .u64 t; cvta.to.shared.u64 t, %1; cvt.u32.u64 %0, t; }" : "=r"(a) : "l"(p));
    return a;
}

// ---------------------------------------------------------------------------
// Pre-split X: fp32 -> hi/lo halves (pure DRAM). grid (4096, 3), 256 thr.
// ---------------------------------------------------------------------------
__global__ __launch_bounds__(256) void presplit_x(
    const float* __restrict__ pre_q, const float* __restrict__ pre_k,
    const float* __restrict__ pre_v)
{
    const int which = blockIdx.y;
    const float* X = which == 0 ? pre_q : which == 1 ? pre_k : pre_v;
    size_t i4 = (size_t)blockIdx.x * 256 + threadIdx.x;
    float4 v = reinterpret_cast<const float4*>(X)[i4];
    size_t o = (size_t)which * 4194304 + i4 * 4;
    __half h0,h1,h2,h3,l0,l1,l2,l3;
    splitf(v.x,h0,l0); splitf(v.y,h1,l1); splitf(v.z,h2,l2); splitf(v.w,h3,l3);
    *reinterpret_cast<__half2*>(gXh + o)     = __halves2half2(h0,h1);
    *reinterpret_cast<__half2*>(gXh + o + 2) = __halves2half2(h2,h3);
    *reinterpret_cast<__half2*>(gXl + o)     = __halves2half2(l0,l1);
    *reinterpret_cast<__half2*>(gXl + o + 2) = __halves2half2(l2,l3);
}

// ---------------------------------------------------------------------------
// Pre-split + transpose W -> [w64][d][k] halves. grid (16, 64), 256 thr.
// ---------------------------------------------------------------------------
__global__ __launch_bounds__(256) void presplit_w(
    const float* __restrict__ Wq, const float* __restrict__ Wk,
    const float* __restrict__ Wv, const float* __restrict__ Wo)
{
    __shared__ float tile[64][65];
    const int tid = threadIdx.x;
    const int w64 = blockIdx.y, k0 = blockIdx.x * 64;
    const float* src; int ld;
    if (w64 < 48) {
        int which = w64 >> 4, h = w64 & 15;
        src = (which == 0 ? Wq : which == 1 ? Wk : Wv) + (size_t)h * kDM * 64;
        ld = 64;
    } else {
        src = Wo + (w64 - 48) * 64;
        ld = 1024;
    }
#pragma unroll
    for (int p = 0; p < 4; p++) {
        int rr = p * 16 + (tid >> 4), c4 = (tid & 15) * 4;
        float4 v = *reinterpret_cast<const float4*>(src + (size_t)(k0 + rr) * ld + c4);
        tile[c4][rr] = v.x; tile[c4+1][rr] = v.y;
        tile[c4+2][rr] = v.z; tile[c4+3][rr] = v.w;
    }
    __syncthreads();
    int d = tid >> 2, kk0 = (tid & 3) * 16;
    size_t base = ((size_t)w64 * 64 + d) * kDM + k0 + kk0;
#pragma unroll
    for (int j = 0; j < 16; j += 2) {
        __half ha,la,hb,lb;
        splitf(tile[d][kk0 + j],     ha, la);
        splitf(tile[d][kk0 + j + 1], hb, lb);
        *reinterpret_cast<__half2*>(gWh + base + j) = __halves2half2(ha, hb);
        *reinterpret_cast<__half2*>(gWl + base + j) = __halves2half2(la, lb);
    }
}

// ---------------------------------------------------------------------------
// cp.async double-buffered 128x128 GEMM mainloop (K=1024, 3-term split).
// ---------------------------------------------------------------------------
DEVI void proj_mainloop(const __half* Ah_s, const __half* Al_s,
                        const __half* Bh_s, const __half* Bl_s,
                        char* sm, uint32_t sb, float acc[2][8][4],
                        int tid, int wm, int wn, int qid, int tq)
{
#pragma unroll 1
    for (int kc = -1; kc < 32; kc++) {
        if (kc >= 0) {
            cpwait0();
            __syncthreads();
        }
        if (kc + 1 < 32) {
            const int stg = (kc + 1) & 1, k0 = (kc + 1) * 32;
#pragma unroll
            for (int i = 0; i < 8; i++) {
                int idx = i * 256 + tid;
                int arr = idx >> 9, rem = idx & 511;
                int r = rem >> 2, ch = rem & 3;
                const __half* s = arr == 0 ? Ah_s : arr == 1 ? Al_s
                                : arr == 2 ? Bh_s : Bl_s;
                cpasync16(sb + stg*40960 + arr*10240 + r*80 + ch*16,
                          s + (size_t)r * kDM + k0 + ch*8);
            }
            cpcommit();
        }
        if (kc < 0) continue;
        const __half* Ah = reinterpret_cast<const __half*>(sm + (kc & 1) * 40960);
        const __half* Al = Ah + 5120;
        const __half* Bh = Al + 5120;
        const __half* Bl = Bh + 5120;
#pragma unroll
        for (int ks = 0; ks < 2; ks++) {
            const int kf = ks * 16;
            uint32_t ahf[2][4], alf[2][4];
#pragma unroll
            for (int mi = 0; mi < 2; mi++) {
                int r = wm*32 + mi*16 + qid;
                load_a(Ah + r*40 + kf + tq*2, 40, ahf[mi]);
                load_a(Al + r*40 + kf + tq*2, 40, alf[mi]);
            }
#pragma unroll
            for (int ni = 0; ni < 8; ni++) {
                int n = wn*64 + ni*8 + qid;
                uint32_t bhf[2], blf[2];
                load_b(Bh + n*40 + kf + tq*2, bhf);
                load_b(Bl + n*40 + kf + tq*2, blf);
#pragma unroll
                for (int mi = 0; mi < 2; mi++) {
                    mma16816(acc[mi][ni], ahf[mi], bhf);
                    mma16816(acc[mi][ni], ahf[mi], blf);
                    mma16816(acc[mi][ni], alf[mi], bhf);
                }
            }
        }
    }
}

// ---------------------------------------------------------------------------
// QKV projections. grid (32, 8, 3). 256 thr.
// ---------------------------------------------------------------------------
__global__ __launch_bounds__(256) void qkv_kernel(
    const float* __restrict__ bq, const float* __restrict__ bk,
    const float* __restrict__ bv)
{
    extern __shared__ __align__(16) char sm[];
    const int tid = threadIdx.x, lane = tid & 31, w = tid >> 5;
    const int wm = w >> 1, wn = w & 1, qid = lane >> 2, tq = lane & 3;
    const int which = blockIdx.z, mbase = blockIdx.x * 128, h0 = blockIdx.y * 2;
    const float* bias = which == 0 ? bq : which == 1 ? bk : bv;

    float acc[2][8][4];
#pragma unroll
    for (int mi = 0; mi < 2; mi++)
#pragma unroll
        for (int ni = 0; ni < 8; ni++)
#pragma unroll
            for (int i = 0; i < 4; i++) acc[mi][ni][i] = 0.f;

    size_t aoff = (size_t)which * 4194304 + (size_t)mbase * kDM;
    size_t boff = ((size_t)(which*16 + h0) * 64) * kDM;
    proj_mainloop(gXh + aoff, gXl + aoff, gWh + boff, gWl + boff,
                  sm, s2u(sm), acc, tid, wm, wn, qid, tq);

    const float qs = (which == 0) ? 0.125f : 1.f;
#pragma unroll
    for (int mi = 0; mi < 2; mi++)
#pragma unroll
        for (int ni = 0; ni < 8; ni++) {
            int r0 = mbase + wm*32 + mi*16 + qid;
            int d0 = wn*64 + ni*8 + tq*2;
            int head = h0 + (d0 >> 6), dd = d0 & 63;
            float bs0 = bias[head*kD + dd], bs1 = bias[head*kD + dd + 1];
#pragma unroll
            for (int hv = 0; hv < 2; hv++) {
                int r = r0 + hv*8, b = r >> 11, s = r & 2047;
                float v0 = acc[mi][ni][hv*2]     + bs0;
                float v1 = acc[mi][ni][hv*2 + 1] + bs1;
                if (which == 2) {
                    __half h0_,l0_,h1_,l1_; splitf(v0,h0_,l0_); splitf(v1,h1_,l1_);
                    size_t a0 = ((size_t)(b*kH + head)*kD + dd)*kS + s;
                    gVh[a0] = h0_; gVl[a0] = l0_;
                    gVh[a0 + kS] = h1_; gVl[a0 + kS] = l1_;
                } else {
                    v0 *= qs; v1 *= qs;
                    __half h0_,l0_,h1_,l1_; splitf(v0,h0_,l0_); splitf(v1,h1_,l1_);
                    size_t a0 = ((size_t)(b*kH + head)*kS + s)*kD + dd;
                    __half* Hh = (which == 0) ? gQh : gKh;
                    __half* Hl = (which == 0) ? gQl : gKl;
                    *reinterpret_cast<__half2*>(Hh + a0) = __halves2half2(h0_,h1_);
                    *reinterpret_cast<__half2*>(Hl + a0) = __halves2half2(l0_,l1_);
                }
            }
        }
}

// ---------------------------------------------------------------------------
// Out-projection. grid (32, 8), 256 thr.
// ---------------------------------------------------------------------------
__global__ __launch_bounds__(256) void outproj_kernel(
    const float* __restrict__ bo, float* __restrict__ out)
{
    extern __shared__ __align__(16) char sm[];
    const int tid = threadIdx.x, lane = tid & 31, w = tid >> 5;
    const int wm = w >> 1, wn = w & 1, qid = lane >> 2, tq = lane & 3;
    const int mbase = blockIdx.x * 128, col0 = blockIdx.y * 128;

    float acc[2][8][4];
#pragma unroll
    for (int mi = 0; mi < 2; mi++)
#pragma unroll
        for (int ni = 0; ni < 8; ni++)
#pragma unroll
            for (int i = 0; i < 4; i++) acc[mi][ni][i] = 0.f;

    size_t aoff = (size_t)mbase * kDM;
    size_t boff = ((size_t)(48*64 + col0)) * kDM;
    proj_mainloop(gCh + aoff, gCl + aoff, gWh + boff, gWl + boff,
                  sm, s2u(sm), acc, tid, wm, wn, qid, tq);
#pragma unroll
    for (int mi = 0; mi < 2; mi++)
#pragma unroll
        for (int ni = 0; ni < 8; ni++) {
            int r0 = mbase + wm*32 + mi*16 + qid;
            int d0 = wn*64 + ni*8 + tq*2;
            float bs0 = bo[col0 + d0], bs1 = bo[col0 + d0 + 1];
#pragma unroll
            for (int hv = 0; hv < 2; hv++) {
                int r = r0 + hv*8;
                out[(size_t)r*kDM + col0 + d0]     = acc[mi][ni][hv*2]     + bs0;
                out[(size_t)r*kDM + col0 + d0 + 1] = acc[mi][ni][hv*2 + 1] + bs1;
            }
        }
}

// ---------------- attention gemms (8 warps, warp tile 32x32) ----------------
DEVI void gemm_score3(const __half* Qh, const __half* Ql,
                      const __half* Kh, const __half* Kl,
                      float cs[2][4][4], int wm, int wn, int qid, int tq) {
#pragma unroll
    for (int kf = 0; kf < 64; kf += 16) {
        uint32_t ah[2][4], al[2][4];
#pragma unroll
        for (int mi = 0; mi < 2; mi++) {
            int r = wm*32 + mi*16 + qid;
            load_a(Qh + r*72 + kf + tq*2, 72, ah[mi]);
            load_a(Ql + r*72 + kf + tq*2, 72, al[mi]);
        }
#pragma unroll
        for (int ni = 0; ni < 4; ni++) {
            int n = wn*32 + ni*8 + qid;
            uint32_t bh[2], bl[2];
            load_b(Kh + n*72 + kf + tq*2, bh);
            load_b(Kl + n*72 + kf + tq*2, bl);
#pragma unroll
            for (int mi = 0; mi < 2; mi++) {
                mma16816(cs[mi][ni], ah[mi], bh);
                mma16816(cs[mi][ni], ah[mi], bl);
                mma16816(cs[mi][ni], al[mi], bh);
            }
        }
    }
}
DEVI void gemm_pv2(const __half* Ph, const __half* Vh, const __half* Vl,
                   float co[2][4][4], int wm, int wn, int qid, int tq) {
#pragma unroll
    for (int kf = 0; kf < 64; kf += 16) {
        uint32_t pa[2][4];
#pragma unroll
        for (int mi = 0; mi < 2; mi++) {
            int r = wm*32 + mi*16 + qid;
            load_a(Ph + r*72 + kf + tq*2, 72, pa[mi]);
        }
#pragma unroll
        for (int ni = 0; ni < 4; ni++) {
            int n = wn*32 + ni*8 + qid;
            uint32_t bh[2], bl[2];
            load_b(Vh + n*72 + kf + tq*2, bh);
            load_b(Vl + n*72 + kf + tq*2, bl);
#pragma unroll
            for (int mi = 0; mi < 2; mi++) {
                mma16816(co[mi][ni], pa[mi], bh);
                mma16816(co[mi][ni], pa[mi], bl);
            }
        }
    }
}

// ---------------------------------------------------------------------------
// Attention: 256 thr, single pass, unnormalized probs (coalesced), 2-term
// P@V, split-O out. Rescale is a SEPARATE wide kernel. grid(16,32).
// ---------------------------------------------------------------------------
__global__ __launch_bounds__(256, 1) void attn_kernel(float* __restrict__ attnOut)
{
    extern __shared__ __align__(16) char sm[];
    __half* Qh = (__half*)sm;                   // 128x72
    __half* Ql = (__half*)(sm + 18432);
    // KV stage s at 36864 + s*36864: Kh,Kl,Vh,Vl each 64x72
    __half* Ph = (__half*)(sm + 110592);        // 128x72
    float* Ssm = (float*)(sm + 129024);         // 128x65
    float* rps = (float*)(sm + 162304);         // 128x2
    float* rl  = (float*)(sm + 163328);         // 128
    float* rnv = (float*)(sm + 163840);         // 128

    const int tid = threadIdx.x, lane = tid & 31, w = tid >> 5;
    const int wm = w >> 1, wn = w & 1, qid = lane >> 2, tq = lane & 3;
    const int bh = blockIdx.y, b = bh >> 4, h = bh & 15;
    const int q0 = blockIdx.x * 128;
    const uint32_t sb = s2u(sm);

    if (tid < 128) rl[tid] = 0.f;
#pragma unroll
    for (int i = 0; i < 8; i++) {               // Q preload
        int arr = i >> 2, wv = ((i & 3) << 8) + tid;
        int r = wv >> 3, j = wv & 7;
        cpasync16(sb + arr*18432 + r*144 + j*16,
                  (arr ? gQl : gQh) + ((size_t)bh*kS + q0 + r)*kD + j*8);
    }
#pragma unroll
    for (int i = 0; i < 8; i++) {               // KV tile 0
        int arr = i >> 1, wv = ((i & 1) << 8) + tid;
        int r = wv >> 3, j = wv & 7;
        const __half* src = arr == 0 ? gKh + ((size_t)bh*kS + r)*kD + j*8
                          : arr == 1 ? gKl + ((size_t)bh*kS + r)*kD + j*8
                          : arr == 2 ? gVh + ((size_t)bh*kD + r)*kS + j*8
                          :            gVl + ((size_t)bh*kD + r)*kS + j*8;
        cpasync16(sb + 36864 + arr*9216 + r*144 + j*16, src);
    }
    cpcommit();

    float co[2][4][4];
#pragma unroll
    for (int mi = 0; mi < 2; mi++)
#pragma unroll
        for (int ni = 0; ni < 4; ni++)
#pragma unroll
            for (int i = 0; i < 4; i++) co[mi][ni][i] = 0.f;

    for (int kt = 0; kt < 32; kt++) {
        const int cur = kt & 1;
        cpwait0();
        __syncthreads();
        if (kt + 1 < 32) {                      // prefetch next KV tile
            const int nxt = cur ^ 1, k1 = (kt + 1) * 64;
#pragma unroll
            for (int i = 0; i < 8; i++) {
                int arr = i >> 1, wv = ((i & 1) << 8) + tid;
                int r = wv >> 3, j = wv & 7;
                const __half* src = arr == 0 ? gKh + ((size_t)bh*kS + k1 + r)*kD + j*8
                                  : arr == 1 ? gKl + ((size_t)bh*kS + k1 + r)*kD + j*8
                                  : arr == 2 ? gVh + ((size_t)bh*kD + r)*kS + k1 + j*8
                                  :            gVl + ((size_t)bh*kD + r)*kS + k1 + j*8;
                cpasync16(sb + 36864 + nxt*36864 + arr*9216 + r*144 + j*16, src);
            }
            cpcommit();
        }
        const __half* Kh = (const __half*)(sm + 36864 + cur*36864);
        const __half* Kl = Kh + 4608;
        const __half* Vh = Kl + 4608;
        const __half* Vl = Vh + 4608;

        float cs[2][4][4];
#pragma unroll
        for (int mi = 0; mi < 2; mi++)
#pragma unroll
            for (int ni = 0; ni < 4; ni++)
#pragma unroll
                for (int i = 0; i < 4; i++) cs[mi][ni][i] = 0.f;
        gemm_score3(Qh, Ql, Kh, Kl, cs, wm, wn, qid, tq);

        // exp in regs -> Ssm (fp32) + Ph (fp16) + rowsum partials
#pragma unroll
        for (int mi = 0; mi < 2; mi++) {
            int ra = wm*32 + mi*16 + qid, rb = ra + 8;
            float pa = 0.f, pb = 0.f;
#pragma unroll
            for (int ni = 0; ni < 4; ni++) {
                int c = wn*32 + ni*8 + tq*2;
                float e0 = fexp(cs[mi][ni][0]), e1 = fexp(cs[mi][ni][1]);
                float e2 = fexp(cs[mi][ni][2]), e3 = fexp(cs[mi][ni][3]);
                Ssm[ra*65 + c] = e0; Ssm[ra*65 + c + 1] = e1;
                Ssm[rb*65 + c] = e2; Ssm[rb*65 + c + 1] = e3;
                *reinterpret_cast<__half2*>(Ph + ra*72 + c) =
                    __halves2half2(__float2half_rn(e0), __float2half_rn(e1));
                *reinterpret_cast<__half2*>(Ph + rb*72 + c) =
                    __halves2half2(__float2half_rn(e2), __float2half_rn(e3));
                pa += e0 + e1; pb += e2 + e3;
            }
            pa += __shfl_xor_sync(0xffffffffu, pa, 1);
            pa += __shfl_xor_sync(0xffffffffu, pa, 2);
            pb += __shfl_xor_sync(0xffffffffu, pb, 1);
            pb += __shfl_xor_sync(0xffffffffu, pb, 2);
            if (tq == 0) { rps[ra*2 + wn] = pa; rps[rb*2 + wn] = pb; }
        }
        __syncthreads();
        if (tid < 128) rl[tid] += rps[tid*2] + rps[tid*2 + 1];

        // unnormalized probs attn[h, kg, b, q] (coalesced in q)
#pragma unroll
        for (int i = 0; i < 32; i++) {
            int kk = i*2 + (tid >> 7);
            int q  = tid & 127;
            attnOut[(((size_t)h*kS + kt*64 + kk)*kB + b)*kS + q0 + q] = Ssm[q*65 + kk];
        }
        gemm_pv2(Ph, Vh, Vl, co, wm, wn, qid, tq);
    }
    __syncthreads();
    if (tid < 128) {
        float inv = 1.f / rl[tid];
        rnv[tid] = inv;
        g_rinv[(size_t)bh*kS + q0 + tid] = inv;
    }
    __syncthreads();

    // O epilogue: normalized, pre-split -> gCh/gCl
#pragma unroll
    for (int mi = 0; mi < 2; mi++)
#pragma unroll
        for (int ni = 0; ni < 4; ni++) {
            int r = wm*32 + mi*16 + qid, d0 = wn*32 + ni*8 + tq*2;
            float i0 = rnv[r], i1 = rnv[r + 8];
            float o0 = co[mi][ni][0]*i0, o1 = co[mi][ni][1]*i0;
            float o2 = co[mi][ni][2]*i1, o3 = co[mi][ni][3]*i1;
            __half h0_,l0_,h1_,l1_,h2_,l2_,h3_,l3_;
            splitf(o0,h0_,l0_); splitf(o1,h1_,l1_);
            splitf(o2,h2_,l2_); splitf(o3,h3_,l3_);
            size_t a0 = ((size_t)(b*kS + q0 + r))*kDM + h*kD + d0;
            size_t a1 = a0 + (size_t)8*kDM;
            *reinterpret_cast<__half2*>(gCh + a0) = __halves2half2(h0_,h1_);
            *reinterpret_cast<__half2*>(gCl + a0) = __halves2half2(l0_,l1_);
            *reinterpret_cast<__half2*>(gCh + a1) = __halves2half2(h2_,h3_);
            *reinterpret_cast<__half2*>(gCl + a1) = __halves2half2(l2_,l3_);
        }
}

// attn[h,k,b,q] *= rinv[b,h,q]  (wide DRAM-bound kernel; FULL coverage)
__global__ __launch_bounds__(256) void rescale_kernel(float* __restrict__ attn)
{
    size_t i4 = (size_t)blockIdx.x * 256 + threadIdx.x;
    size_t flat = i4 * 4;
    int q = (int)(flat & 2047);
    int b = (int)((flat >> 11) & 1);
    int h = (int)(flat >> 23);
    float4 rv = *reinterpret_cast<const float4*>(
        g_rinv + ((size_t)(b*kH + h)) * kS + q);
    float4 v = *reinterpret_cast<float4*>(attn + flat);
    v.x *= rv.x; v.y *= rv.y; v.z *= rv.z; v.w *= rv.w;
    *reinterpret_cast<float4*>(attn + flat) = v;
}

// ---------------------------------------------------------------------------
extern "C" void kernel_launch(void* const* d_in, const int* in_sizes, int n_in,
                              void* d_out, int out_size) {
    const float* pre_q = (const float*)d_in[0];
    const float* pre_k = (const float*)d_in[1];
    const float* pre_v = (const float*)d_in[2];
    const float* Wq = (const float*)d_in[4];
    const float* bq = (const float*)d_in[5];
    const float* Wk = (const float*)d_in[6];
    const float* bk = (const float*)d_in[7];
    const float* Wv = (const float*)d_in[8];
    const float* bv = (const float*)d_in[9];
    const float* Wo = (const float*)d_in[10];
    const float* bo = (const float*)d_in[11];

    float* out  = (float*)d_out;
    float* attn = out + (size_t)kB * kS * kDM;

    cudaFuncSetAttribute(attn_kernel,
                         cudaFuncAttributeMaxDynamicSharedMemorySize, ATTN_SMEM);
    cudaFuncSetAttribute(qkv_kernel,
                         cudaFuncAttributeMaxDynamicSharedMemorySize, PROJ_SMEM);
    cudaFuncSetAttribute(outproj_kernel,
                         cudaFuncAttributeMaxDynamicSharedMemorySize, PROJ_SMEM);

    presplit_x<<<dim3(4096, 3), 256>>>(pre_q, pre_k, pre_v);
    presplit_w<<<dim3(16, 64), 256>>>(Wq, Wk, Wv, Wo);
    qkv_kernel<<<dim3(32, 8, 3), 256, PROJ_SMEM>>>(bq, bk, bv);
    attn_kernel<<<dim3(16, 32), 256, ATTN_SMEM>>>(attn);
    // FULL coverage: kH*kS*kB*kS elements / (4 per thread * 256 threads)
    rescale_kernel<<<((size_t)kH * kS * kB * kS) / (4 * 256), 256>>>(attn);
    outproj_kernel<<<dim3(32, 8), 256, PROJ_SMEM>>>(bo, out);
}

// round 16
// speedup vs baseline: 1.6219x; 1.0609x over previous
#include <cuda_runtime.h>
#include <cuda_fp16.h>
#include <stdint.h>

#define DEVI __device__ __forceinline__

namespace {
constexpr int kB = 2, kS = 2048, kDM = 1024, kH = 16, kD = 64;
constexpr int kBS = kB * kS, kBH = kB * kH;
constexpr int kQB = kB * kS;              // float stride between adjacent k rows
constexpr int ATTN_SMEM = 131072;
constexpr int PROJ_SMEM = 81920;
}

// ---------------- static scratch ----------------
__device__ __half gXh[(size_t)3*kBS*kDM], gXl[(size_t)3*kBS*kDM]; // [which][r][k]
__device__ __half gWh[(size_t)64*64*kDM], gWl[(size_t)64*64*kDM]; // [w64][d][k] (48.. = Wo)
__device__ __half gQh[(size_t)kBH*kS*kD], gQl[(size_t)kBH*kS*kD]; // [bh][s][d] (x0.125)
__device__ __half gKh[(size_t)kBH*kS*kD], gKl[(size_t)kBH*kS*kD]; // [bh][s][d]
__device__ __half gVh[(size_t)kBH*kD*kS], gVl[(size_t)kBH*kD*kS]; // [bh][d][s]
__device__ __half gCh[(size_t)kBS*kDM],  gCl[(size_t)kBS*kDM];    // concat O (split)
__device__ float  g_rinv[(size_t)kBH*kS];                         // 1/rowsum

// ---------------- helpers ----------------
DEVI void mma16816(float c[4], const uint32_t a[4], const uint32_t b[2]) {
    asm volatile(
        "mma.sync.aligned.m16n8k16.row.col.f32.f16.f16.f32 "
        "{%0,%1,%2,%3}, {%4,%5,%6,%7}, {%8,%9}, {%0,%1,%2,%3};\n"
        : "+f"(c[0]), "+f"(c[1]), "+f"(c[2]), "+f"(c[3])
        : "r"(a[0]), "r"(a[1]), "r"(a[2]), "r"(a[3]), "r"(b[0]), "r"(b[1]));
}
DEVI void splitf(float x, __half& hi, __half& lo) {
    hi = __float2half_rn(x);
    lo = __float2half_rn(x - __half2float(hi));
}
DEVI void load_a(const __half* base, int st, uint32_t a[4]) {
    a[0] = *reinterpret_cast<const uint32_t*>(base);
    a[1] = *reinterpret_cast<const uint32_t*>(base + 8 * st);
    a[2] = *reinterpret_cast<const uint32_t*>(base + 8);
    a[3] = *reinterpret_cast<const uint32_t*>(base + 8 * st + 8);
}
DEVI void load_b(const __half* base, uint32_t b[2]) {
    b[0] = *reinterpret_cast<const uint32_t*>(base);
    b[1] = *reinterpret_cast<const uint32_t*>(base + 8);
}
DEVI float fexp(float x) {   // FFMA-only exp, |rel err| ~1e-7
    float t = x * 1.44269504f;
    float fn = rintf(t);
    float f = t - fn;
    float p = 1.33336498e-3f;
    p = fmaf(p, f, 9.61793093e-3f);
    p = fmaf(p, f, 5.55043924e-2f);
    p = fmaf(p, f, 2.40226507e-1f);
    p = fmaf(p, f, 6.93147182e-1f);
    p = fmaf(p, f, 1.0f);
    return __int_as_float(__float_as_int(p) + (((int)fn) << 23));
}
DEVI void cpasync16(uint32_t dst, const void* src) {
    asm volatile("cp.async.cg.shared.global [%0], [%1], 16;\n" :: "r"(dst), "l"(src));
}
DEVI void cpcommit() { asm volatile("cp.async.commit_group;\n" ::: "memory"); }
DEVI void cpwait0()  { asm volatile("cp.async.wait_group 0;\n" ::: "memory"); }
DEVI uint32_t s2u(const void* p) {
    uint32_t a;
    asm("{ .reg .u64 t; cvta.to.shared.u64 t, %1; cvt.u32.u64 %0, t; }" : "=r"(a) : "l"(p));
    return a;
}

// ---------------------------------------------------------------------------
// Pre-split X: fp32 -> hi/lo halves (pure DRAM). grid (4096, 3), 256 thr.
// ---------------------------------------------------------------------------
__global__ __launch_bounds__(256) void presplit_x(
    const float* __restrict__ pre_q, const float* __restrict__ pre_k,
    const float* __restrict__ pre_v)
{
    const int which = blockIdx.y;
    const float* X = which == 0 ? pre_q : which == 1 ? pre_k : pre_v;
    size_t i4 = (size_t)blockIdx.x * 256 + threadIdx.x;
    float4 v = reinterpret_cast<const float4*>(X)[i4];
    size_t o = (size_t)which * 4194304 + i4 * 4;
    __half h0,h1,h2,h3,l0,l1,l2,l3;
    splitf(v.x,h0,l0); splitf(v.y,h1,l1); splitf(v.z,h2,l2); splitf(v.w,h3,l3);
    *reinterpret_cast<__half2*>(gXh + o)     = __halves2half2(h0,h1);
    *reinterpret_cast<__half2*>(gXh + o + 2) = __halves2half2(h2,h3);
    *reinterpret_cast<__half2*>(gXl + o)     = __halves2half2(l0,l1);
    *reinterpret_cast<__half2*>(gXl + o + 2) = __halves2half2(l2,l3);
}

// ---------------------------------------------------------------------------
// Pre-split + transpose W -> [w64][d][k] halves. grid (16, 64), 256 thr.
// ---------------------------------------------------------------------------
__global__ __launch_bounds__(256) void presplit_w(
    const float* __restrict__ Wq, const float* __restrict__ Wk,
    const float* __restrict__ Wv, const float* __restrict__ Wo)
{
    __shared__ float tile[64][65];
    const int tid = threadIdx.x;
    const int w64 = blockIdx.y, k0 = blockIdx.x * 64;
    const float* src; int ld;
    if (w64 < 48) {
        int which = w64 >> 4, h = w64 & 15;
        src = (which == 0 ? Wq : which == 1 ? Wk : Wv) + (size_t)h * kDM * 64;
        ld = 64;
    } else {
        src = Wo + (w64 - 48) * 64;
        ld = 1024;
    }
#pragma unroll
    for (int p = 0; p < 4; p++) {
        int rr = p * 16 + (tid >> 4), c4 = (tid & 15) * 4;
        float4 v = *reinterpret_cast<const float4*>(src + (size_t)(k0 + rr) * ld + c4);
        tile[c4][rr] = v.x; tile[c4+1][rr] = v.y;
        tile[c4+2][rr] = v.z; tile[c4+3][rr] = v.w;
    }
    __syncthreads();
    int d = tid >> 2, kk0 = (tid & 3) * 16;
    size_t base = ((size_t)w64 * 64 + d) * kDM + k0 + kk0;
#pragma unroll
    for (int j = 0; j < 16; j += 2) {
        __half ha,la,hb,lb;
        splitf(tile[d][kk0 + j],     ha, la);
        splitf(tile[d][kk0 + j + 1], hb, lb);
        *reinterpret_cast<__half2*>(gWh + base + j) = __halves2half2(ha, hb);
        *reinterpret_cast<__half2*>(gWl + base + j) = __halves2half2(la, lb);
    }
}

// ---------------------------------------------------------------------------
// cp.async double-buffered 128x128 GEMM mainloop (K=1024, 3-term split).
// ---------------------------------------------------------------------------
DEVI void proj_mainloop(const __half* Ah_s, const __half* Al_s,
                        const __half* Bh_s, const __half* Bl_s,
                        char* sm, uint32_t sb, float acc[2][8][4],
                        int tid, int wm, int wn, int qid, int tq)
{
#pragma unroll 1
    for (int kc = -1; kc < 32; kc++) {
        if (kc >= 0) {
            cpwait0();
            __syncthreads();
        }
        if (kc + 1 < 32) {
            const int stg = (kc + 1) & 1, k0 = (kc + 1) * 32;
#pragma unroll
            for (int i = 0; i < 8; i++) {
                int idx = i * 256 + tid;
                int arr = idx >> 9, rem = idx & 511;
                int r = rem >> 2, ch = rem & 3;
                const __half* s = arr == 0 ? Ah_s : arr == 1 ? Al_s
                                : arr == 2 ? Bh_s : Bl_s;
                cpasync16(sb + stg*40960 + arr*10240 + r*80 + ch*16,
                          s + (size_t)r * kDM + k0 + ch*8);
            }
            cpcommit();
        }
        if (kc < 0) continue;
        const __half* Ah = reinterpret_cast<const __half*>(sm + (kc & 1) * 40960);
        const __half* Al = Ah + 5120;
        const __half* Bh = Al + 5120;
        const __half* Bl = Bh + 5120;
#pragma unroll
        for (int ks = 0; ks < 2; ks++) {
            const int kf = ks * 16;
            uint32_t ahf[2][4], alf[2][4];
#pragma unroll
            for (int mi = 0; mi < 2; mi++) {
                int r = wm*32 + mi*16 + qid;
                load_a(Ah + r*40 + kf + tq*2, 40, ahf[mi]);
                load_a(Al + r*40 + kf + tq*2, 40, alf[mi]);
            }
#pragma unroll
            for (int ni = 0; ni < 8; ni++) {
                int n = wn*64 + ni*8 + qid;
                uint32_t bhf[2], blf[2];
                load_b(Bh + n*40 + kf + tq*2, bhf);
                load_b(Bl + n*40 + kf + tq*2, blf);
#pragma unroll
                for (int mi = 0; mi < 2; mi++) {
                    mma16816(acc[mi][ni], ahf[mi], bhf);
                    mma16816(acc[mi][ni], ahf[mi], blf);
                    mma16816(acc[mi][ni], alf[mi], bhf);
                }
            }
        }
    }
}

// ---------------------------------------------------------------------------
// QKV projections. grid (32, 8, 3). 256 thr.
// ---------------------------------------------------------------------------
__global__ __launch_bounds__(256) void qkv_kernel(
    const float* __restrict__ bq, const float* __restrict__ bk,
    const float* __restrict__ bv)
{
    extern __shared__ __align__(16) char sm[];
    const int tid = threadIdx.x, lane = tid & 31, w = tid >> 5;
    const int wm = w >> 1, wn = w & 1, qid = lane >> 2, tq = lane & 3;
    const int which = blockIdx.z, mbase = blockIdx.x * 128, h0 = blockIdx.y * 2;
    const float* bias = which == 0 ? bq : which == 1 ? bk : bv;

    float acc[2][8][4];
#pragma unroll
    for (int mi = 0; mi < 2; mi++)
#pragma unroll
        for (int ni = 0; ni < 8; ni++)
#pragma unroll
            for (int i = 0; i < 4; i++) acc[mi][ni][i] = 0.f;

    size_t aoff = (size_t)which * 4194304 + (size_t)mbase * kDM;
    size_t boff = ((size_t)(which*16 + h0) * 64) * kDM;
    proj_mainloop(gXh + aoff, gXl + aoff, gWh + boff, gWl + boff,
                  sm, s2u(sm), acc, tid, wm, wn, qid, tq);

    const float qs = (which == 0) ? 0.125f : 1.f;
#pragma unroll
    for (int mi = 0; mi < 2; mi++)
#pragma unroll
        for (int ni = 0; ni < 8; ni++) {
            int r0 = mbase + wm*32 + mi*16 + qid;
            int d0 = wn*64 + ni*8 + tq*2;
            int head = h0 + (d0 >> 6), dd = d0 & 63;
            float bs0 = bias[head*kD + dd], bs1 = bias[head*kD + dd + 1];
#pragma unroll
            for (int hv = 0; hv < 2; hv++) {
                int r = r0 + hv*8, b = r >> 11, s = r & 2047;
                float v0 = acc[mi][ni][hv*2]     + bs0;
                float v1 = acc[mi][ni][hv*2 + 1] + bs1;
                if (which == 2) {
                    __half h0_,l0_,h1_,l1_; splitf(v0,h0_,l0_); splitf(v1,h1_,l1_);
                    size_t a0 = ((size_t)(b*kH + head)*kD + dd)*kS + s;
                    gVh[a0] = h0_; gVl[a0] = l0_;
                    gVh[a0 + kS] = h1_; gVl[a0 + kS] = l1_;
                } else {
                    v0 *= qs; v1 *= qs;
                    __half h0_,l0_,h1_,l1_; splitf(v0,h0_,l0_); splitf(v1,h1_,l1_);
                    size_t a0 = ((size_t)(b*kH + head)*kS + s)*kD + dd;
                    __half* Hh = (which == 0) ? gQh : gKh;
                    __half* Hl = (which == 0) ? gQl : gKl;
                    *reinterpret_cast<__half2*>(Hh + a0) = __halves2half2(h0_,h1_);
                    *reinterpret_cast<__half2*>(Hl + a0) = __halves2half2(l0_,l1_);
                }
            }
        }
}

// ---------------------------------------------------------------------------
// Out-projection. grid (32, 8), 256 thr.
// ---------------------------------------------------------------------------
__global__ __launch_bounds__(256) void outproj_kernel(
    const float* __restrict__ bo, float* __restrict__ out)
{
    extern __shared__ __align__(16) char sm[];
    const int tid = threadIdx.x, lane = tid & 31, w = tid >> 5;
    const int wm = w >> 1, wn = w & 1, qid = lane >> 2, tq = lane & 3;
    const int mbase = blockIdx.x * 128, col0 = blockIdx.y * 128;

    float acc[2][8][4];
#pragma unroll
    for (int mi = 0; mi < 2; mi++)
#pragma unroll
        for (int ni = 0; ni < 8; ni++)
#pragma unroll
            for (int i = 0; i < 4; i++) acc[mi][ni][i] = 0.f;

    size_t aoff = (size_t)mbase * kDM;
    size_t boff = ((size_t)(48*64 + col0)) * kDM;
    proj_mainloop(gCh + aoff, gCl + aoff, gWh + boff, gWl + boff,
                  sm, s2u(sm), acc, tid, wm, wn, qid, tq);
#pragma unroll
    for (int mi = 0; mi < 2; mi++)
#pragma unroll
        for (int ni = 0; ni < 8; ni++) {
            int r0 = mbase + wm*32 + mi*16 + qid;
            int d0 = wn*64 + ni*8 + tq*2;
            float bs0 = bo[col0 + d0], bs1 = bo[col0 + d0 + 1];
#pragma unroll
            for (int hv = 0; hv < 2; hv++) {
                int r = r0 + hv*8;
                out[(size_t)r*kDM + col0 + d0]     = acc[mi][ni][hv*2]     + bs0;
                out[(size_t)r*kDM + col0 + d0 + 1] = acc[mi][ni][hv*2 + 1] + bs1;
            }
        }
}

// ---------------- attention gemms (8 warps, warp tile 32x32) ----------------
DEVI void gemm_score3(const __half* Qh, const __half* Ql,
                      const __half* Kh, const __half* Kl,
                      float cs[2][4][4], int wm, int wn, int qid, int tq) {
#pragma unroll
    for (int kf = 0; kf < 64; kf += 16) {
        uint32_t ah[2][4], al[2][4];
#pragma unroll
        for (int mi = 0; mi < 2; mi++) {
            int r = wm*32 + mi*16 + qid;
            load_a(Qh + r*72 + kf + tq*2, 72, ah[mi]);
            load_a(Ql + r*72 + kf + tq*2, 72, al[mi]);
        }
#pragma unroll
        for (int ni = 0; ni < 4; ni++) {
            int n = wn*32 + ni*8 + qid;
            uint32_t bh[2], bl[2];
            load_b(Kh + n*72 + kf + tq*2, bh);
            load_b(Kl + n*72 + kf + tq*2, bl);
#pragma unroll
            for (int mi = 0; mi < 2; mi++) {
                mma16816(cs[mi][ni], ah[mi], bh);
                mma16816(cs[mi][ni], ah[mi], bl);
                mma16816(cs[mi][ni], al[mi], bh);
            }
        }
    }
}
DEVI void gemm_pv2(const __half* Ph, const __half* Vh, const __half* Vl,
                   float co[2][4][4], int wm, int wn, int qid, int tq) {
#pragma unroll
    for (int kf = 0; kf < 64; kf += 16) {
        uint32_t pa[2][4];
#pragma unroll
        for (int mi = 0; mi < 2; mi++) {
            int r = wm*32 + mi*16 + qid;
            load_a(Ph + r*72 + kf + tq*2, 72, pa[mi]);
        }
#pragma unroll
        for (int ni = 0; ni < 4; ni++) {
            int n = wn*32 + ni*8 + qid;
            uint32_t bh[2], bl[2];
            load_b(Vh + n*72 + kf + tq*2, bh);
            load_b(Vl + n*72 + kf + tq*2, bl);
#pragma unroll
            for (int mi = 0; mi < 2; mi++) {
                mma16816(co[mi][ni], pa[mi], bh);
                mma16816(co[mi][ni], pa[mi], bl);
            }
        }
    }
}

// ---------------------------------------------------------------------------
// Attention: 256 thr, single pass, unnormalized probs stored DIRECT from
// registers (no Ssm staging), 2-term P@V, split-O out. grid(16,32), 131KB.
// ---------------------------------------------------------------------------
__global__ __launch_bounds__(256, 1) void attn_kernel(float* __restrict__ attnOut)
{
    extern __shared__ __align__(16) char sm[];
    __half* Qh = (__half*)sm;                   // 128x72
    __half* Ql = (__half*)(sm + 18432);
    // KV stage s at 36864 + s*36864: Kh,Kl,Vh,Vl each 64x72
    __half* Ph = (__half*)(sm + 110592);        // 128x72
    float* rps = (float*)(sm + 129024);         // 128x2
    float* rl  = (float*)(sm + 130048);         // 128
    float* rnv = (float*)(sm + 130560);         // 128

    const int tid = threadIdx.x, lane = tid & 31, w = tid >> 5;
    const int wm = w >> 1, wn = w & 1, qid = lane >> 2, tq = lane & 3;
    const int bh = blockIdx.y, b = bh >> 4, h = bh & 15;
    const int q0 = blockIdx.x * 128;
    const uint32_t sb = s2u(sm);

    if (tid < 128) rl[tid] = 0.f;
#pragma unroll
    for (int i = 0; i < 8; i++) {               // Q preload
        int arr = i >> 2, wv = ((i & 3) << 8) + tid;
        int r = wv >> 3, j = wv & 7;
        cpasync16(sb + arr*18432 + r*144 + j*16,
                  (arr ? gQl : gQh) + ((size_t)bh*kS + q0 + r)*kD + j*8);
    }
#pragma unroll
    for (int i = 0; i < 8; i++) {               // KV tile 0
        int arr = i >> 1, wv = ((i & 1) << 8) + tid;
        int r = wv >> 3, j = wv & 7;
        const __half* src = arr == 0 ? gKh + ((size_t)bh*kS + r)*kD + j*8
                          : arr == 1 ? gKl + ((size_t)bh*kS + r)*kD + j*8
                          : arr == 2 ? gVh + ((size_t)bh*kD + r)*kS + j*8
                          :            gVl + ((size_t)bh*kD + r)*kS + j*8;
        cpasync16(sb + 36864 + arr*9216 + r*144 + j*16, src);
    }
    cpcommit();

    float co[2][4][4];
#pragma unroll
    for (int mi = 0; mi < 2; mi++)
#pragma unroll
        for (int ni = 0; ni < 4; ni++)
#pragma unroll
            for (int i = 0; i < 4; i++) co[mi][ni][i] = 0.f;

    for (int kt = 0; kt < 32; kt++) {
        const int cur = kt & 1;
        cpwait0();
        __syncthreads();
        if (kt + 1 < 32) {                      // prefetch next KV tile
            const int nxt = cur ^ 1, k1 = (kt + 1) * 64;
#pragma unroll
            for (int i = 0; i < 8; i++) {
                int arr = i >> 1, wv = ((i & 1) << 8) + tid;
                int r = wv >> 3, j = wv & 7;
                const __half* src = arr == 0 ? gKh + ((size_t)bh*kS + k1 + r)*kD + j*8
                                  : arr == 1 ? gKl + ((size_t)bh*kS + k1 + r)*kD + j*8
                                  : arr == 2 ? gVh + ((size_t)bh*kD + r)*kS + k1 + j*8
                                  :            gVl + ((size_t)bh*kD + r)*kS + k1 + j*8;
                cpasync16(sb + 36864 + nxt*36864 + arr*9216 + r*144 + j*16, src);
            }
            cpcommit();
        }
        const __half* Kh = (const __half*)(sm + 36864 + cur*36864);
        const __half* Kl = Kh + 4608;
        const __half* Vh = Kl + 4608;
        const __half* Vl = Vh + 4608;

        float cs[2][4][4];
#pragma unroll
        for (int mi = 0; mi < 2; mi++)
#pragma unroll
            for (int ni = 0; ni < 4; ni++)
#pragma unroll
                for (int i = 0; i < 4; i++) cs[mi][ni][i] = 0.f;
        gemm_score3(Qh, Ql, Kh, Kl, cs, wm, wn, qid, tq);

        // exp in regs -> gmem probs DIRECT (unnormalized, 32B sectors)
        //              + Ph (fp16) + rowsum partials
        // attn[h, kg, b, q] layout: adjacent k rows are kQB floats apart.
#pragma unroll
        for (int mi = 0; mi < 2; mi++) {
            int ra = wm*32 + mi*16 + qid, rb = ra + 8;
            float pa = 0.f, pb = 0.f;
#pragma unroll
            for (int ni = 0; ni < 4; ni++) {
                int c = wn*32 + ni*8 + tq*2;
                float e0 = fexp(cs[mi][ni][0]), e1 = fexp(cs[mi][ni][1]);
                float e2 = fexp(cs[mi][ni][2]), e3 = fexp(cs[mi][ni][3]);
                size_t a = (((size_t)h*kS + kt*64 + c)*kB + b)*kS + q0;
                attnOut[a + ra]       = e0;     // (kg=c,   q=ra)
                attnOut[a + kQB + ra] = e1;     // (kg=c+1, q=ra)
                attnOut[a + rb]       = e2;     // (kg=c,   q=rb)
                attnOut[a + kQB + rb] = e3;     // (kg=c+1, q=rb)
                *reinterpret_cast<__half2*>(Ph + ra*72 + c) =
                    __halves2half2(__float2half_rn(e0), __float2half_rn(e1));
                *reinterpret_cast<__half2*>(Ph + rb*72 + c) =
                    __halves2half2(__float2half_rn(e2), __float2half_rn(e3));
                pa += e0 + e1; pb += e2 + e3;
            }
            pa += __shfl_xor_sync(0xffffffffu, pa, 1);
            pa += __shfl_xor_sync(0xffffffffu, pa, 2);
            pb += __shfl_xor_sync(0xffffffffu, pb, 1);
            pb += __shfl_xor_sync(0xffffffffu, pb, 2);
            if (tq == 0) { rps[ra*2 + wn] = pa; rps[rb*2 + wn] = pb; }
        }
        __syncthreads();
        if (tid < 128) rl[tid] += rps[tid*2] + rps[tid*2 + 1];

        gemm_pv2(Ph, Vh, Vl, co, wm, wn, qid, tq);
    }
    __syncthreads();
    if (tid < 128) {
        float inv = 1.f / rl[tid];
        rnv[tid] = inv;
        g_rinv[(size_t)bh*kS + q0 + tid] = inv;
    }
    __syncthreads();

    // O epilogue: normalized, pre-split -> gCh/gCl
#pragma unroll
    for (int mi = 0; mi < 2; mi++)
#pragma unroll
        for (int ni = 0; ni < 4; ni++) {
            int r = wm*32 + mi*16 + qid, d0 = wn*32 + ni*8 + tq*2;
            float i0 = rnv[r], i1 = rnv[r + 8];
            float o0 = co[mi][ni][0]*i0, o1 = co[mi][ni][1]*i0;
            float o2 = co[mi][ni][2]*i1, o3 = co[mi][ni][3]*i1;
            __half h0_,l0_,h1_,l1_,h2_,l2_,h3_,l3_;
            splitf(o0,h0_,l0_); splitf(o1,h1_,l1_);
            splitf(o2,h2_,l2_); splitf(o3,h3_,l3_);
            size_t a0 = ((size_t)(b*kS + q0 + r))*kDM + h*kD + d0;
            size_t a1 = a0 + (size_t)8*kDM;
            *reinterpret_cast<__half2*>(gCh + a0) = __halves2half2(h0_,h1_);
            *reinterpret_cast<__half2*>(gCl + a0) = __halves2half2(l0_,l1_);
            *reinterpret_cast<__half2*>(gCh + a1) = __halves2half2(h2_,h3_);
            *reinterpret_cast<__half2*>(gCl + a1) = __halves2half2(l2_,l3_);
        }
}

// attn[h,k,b,q] *= rinv[b,h,q]  (wide DRAM-bound kernel; FULL coverage)
__global__ __launch_bounds__(256) void rescale_kernel(float* __restrict__ attn)
{
    size_t i4 = (size_t)blockIdx.x * 256 + threadIdx.x;
    size_t flat = i4 * 4;
    int q = (int)(flat & 2047);
    int b = (int)((flat >> 11) & 1);
    int h = (int)(flat >> 23);
    float4 rv = *reinterpret_cast<const float4*>(
        g_rinv + ((size_t)(b*kH + h)) * kS + q);
    float4 v = *reinterpret_cast<float4*>(attn + flat);
    v.x *= rv.x; v.y *= rv.y; v.z *= rv.z; v.w *= rv.w;
    *reinterpret_cast<float4*>(attn + flat) = v;
}

// ---------------------------------------------------------------------------
extern "C" void kernel_launch(void* const* d_in, const int* in_sizes, int n_in,
                              void* d_out, int out_size) {
    const float* pre_q = (const float*)d_in[0];
    const float* pre_k = (const float*)d_in[1];
    const float* pre_v = (const float*)d_in[2];
    const float* Wq = (const float*)d_in[4];
    const float* bq = (const float*)d_in[5];
    const float* Wk = (const float*)d_in[6];
    const float* bk = (const float*)d_in[7];
    const float* Wv = (const float*)d_in[8];
    const float* bv = (const float*)d_in[9];
    const float* Wo = (const float*)d_in[10];
    const float* bo = (const float*)d_in[11];

    float* out  = (float*)d_out;
    float* attn = out + (size_t)kB * kS * kDM;

    cudaFuncSetAttribute(attn_kernel,
                         cudaFuncAttributeMaxDynamicSharedMemorySize, ATTN_SMEM);
    cudaFuncSetAttribute(qkv_kernel,
                         cudaFuncAttributeMaxDynamicSharedMemorySize, PROJ_SMEM);
    cudaFuncSetAttribute(outproj_kernel,
                         cudaFuncAttributeMaxDynamicSharedMemorySize, PROJ_SMEM);

    presplit_x<<<dim3(4096, 3), 256>>>(pre_q, pre_k, pre_v);
    presplit_w<<<dim3(16, 64), 256>>>(Wq, Wk, Wv, Wo);
    qkv_kernel<<<dim3(32, 8, 3), 256, PROJ_SMEM>>>(bq, bk, bv);
    attn_kernel<<<dim3(16, 32), 256, ATTN_SMEM>>>(attn);
    // FULL coverage: kH*kS*kB*kS elements / (4 per thread * 256 threads)
    rescale_kernel<<<((size_t)kH * kS * kB * kS) / (4 * 256), 256>>>(attn);
    outproj_kernel<<<dim3(32, 8), 256, PROJ_SMEM>>>(bo, out);
}